// round 11
// baseline (speedup 1.0000x reference)
#include <cuda_runtime.h>
#include <cuda_bf16.h>
#include <mma.h>
#include <math.h>
#include <stdint.h>

using namespace nvcuda;

// Problem constants
#define BB 2
#define SS 2048
#define DD 1024
#define HH 16
#define HD 64
#define MROWS (BB*SS)      // 4096
#define NELEM (BB*SS*DD)   // 4M
#define WELEM (DD*DD)      // 1M

// ---------------------------------------------------------------------------
// Global scratch (allocation-free rule: __device__ globals), all bf16 hi/lo
// ---------------------------------------------------------------------------
__device__ __nv_bfloat16 g_iqh[NELEM], g_iql[NELEM];
__device__ __nv_bfloat16 g_ikh[NELEM], g_ikl[NELEM];
__device__ __nv_bfloat16 g_ivh[NELEM], g_ivl[NELEM];
__device__ __nv_bfloat16 g_wqh[WELEM], g_wql[WELEM];
__device__ __nv_bfloat16 g_wkh[WELEM], g_wkl[WELEM];
__device__ __nv_bfloat16 g_wvh[WELEM], g_wvl[WELEM];
__device__ __nv_bfloat16 g_woh[WELEM], g_wol[WELEM];
__device__ __nv_bfloat16 g_Qh[NELEM], g_Ql[NELEM];
__device__ __nv_bfloat16 g_Kh[NELEM], g_Kl[NELEM];
__device__ __nv_bfloat16 g_Vh[NELEM], g_Vl[NELEM];
__device__ __nv_bfloat16 g_Ch[NELEM], g_Cl[NELEM];

__device__ __forceinline__ void bsplit4(float4 v, uint2& h, uint2& l) {
    __nv_bfloat162 h0, h1, l0, l1;
    h0.x = __float2bfloat16(v.x); h0.y = __float2bfloat16(v.y);
    h1.x = __float2bfloat16(v.z); h1.y = __float2bfloat16(v.w);
    l0.x = __float2bfloat16(v.x - __bfloat162float(h0.x));
    l0.y = __float2bfloat16(v.y - __bfloat162float(h0.y));
    l1.x = __float2bfloat16(v.z - __bfloat162float(h1.x));
    l1.y = __float2bfloat16(v.w - __bfloat162float(h1.y));
    h.x = *(uint32_t*)&h0; h.y = *(uint32_t*)&h1;
    l.x = *(uint32_t*)&l0; l.y = *(uint32_t*)&l1;
}

__device__ __forceinline__ void split2(float x, float y, uint32_t& hi, uint32_t& lo) {
    uint32_t h;
    asm("cvt.rn.bf16x2.f32 %0, %1, %2;" : "=r"(h) : "f"(y), "f"(x));
    float hx = __uint_as_float(h << 16);
    float hy = __uint_as_float(h & 0xffff0000u);
    uint32_t l;
    asm("cvt.rn.bf16x2.f32 %0, %1, %2;" : "=r"(l) : "f"(y - hy), "f"(x - hx));
    hi = h; lo = l;
}

__device__ __forceinline__ uint32_t smem_u32(const void* p) {
    uint32_t a;
    asm("{ .reg .u64 t; cvta.to.shared.u64 t, %1; cvt.u32.u64 %0, t; }"
        : "=r"(a) : "l"(p));
    return a;
}
__device__ __forceinline__ void cp16(uint32_t dst, const void* src) {
    asm volatile("cp.async.cg.shared.global [%0], [%1], 16;" :: "r"(dst), "l"(src));
}
__device__ __forceinline__ void ldsm_x4(uint32_t* r, uint32_t addr) {
    asm volatile("ldmatrix.sync.aligned.m8n8.x4.shared.b16 {%0,%1,%2,%3}, [%4];"
        : "=r"(r[0]), "=r"(r[1]), "=r"(r[2]), "=r"(r[3]) : "r"(addr));
}
__device__ __forceinline__ void ldsm_x4_t(uint32_t* r, uint32_t addr) {
    asm volatile("ldmatrix.sync.aligned.m8n8.x4.trans.shared.b16 {%0,%1,%2,%3}, [%4];"
        : "=r"(r[0]), "=r"(r[1]), "=r"(r[2]), "=r"(r[3]) : "r"(addr));
}
__device__ __forceinline__ void mma16816(float* c, const uint32_t* a, uint32_t b0, uint32_t b1) {
    asm volatile(
        "mma.sync.aligned.m16n8k16.row.col.f32.bf16.bf16.f32 "
        "{%0,%1,%2,%3}, {%4,%5,%6,%7}, {%8,%9}, {%0,%1,%2,%3};"
        : "+f"(c[0]), "+f"(c[1]), "+f"(c[2]), "+f"(c[3])
        : "r"(a[0]), "r"(a[1]), "r"(a[2]), "r"(a[3]), "r"(b0), "r"(b1));
}

// ===========================================================================
// Split kernel: fp32 -> bf16 hi/lo, vectorized.
// ===========================================================================
__global__ __launch_bounds__(256) void split_k(
    const float* __restrict__ x, __nv_bfloat16* __restrict__ h,
    __nv_bfloat16* __restrict__ l, int n4)
{
    int i = blockIdx.x * blockDim.x + threadIdx.x;
    if (i < n4) {
        float4 v = ((const float4*)x)[i];
        uint2 hh, ll;
        bsplit4(v, hh, ll);
        ((uint2*)h)[i] = hh;
        ((uint2*)l)[i] = ll;
    }
}

// ===========================================================================
// GEMM mainloop (shared by QKV-fused and Wo kernels).
// 128x128 tile, BK=32, 3-stage cp.async, 8 warps (4x2), warp tile 32x64.
// ===========================================================================
#define BK 32
#define NC (DD / BK)       // 32
#define LDAs 40
#define LDBs 136
#define STG_A (128 * LDAs)
#define STG_B (BK * LDBs)
#define OFF_AL (STG_A * 2)
#define OFF_BH (2 * STG_A * 2)
#define OFF_BL (2 * STG_A * 2 + STG_B * 2)
#define STG_BYTES ((2 * STG_A + 2 * STG_B) * 2)   // 37888
#define GEMM_SMEM (3 * STG_BYTES)                  // 113664

__device__ __forceinline__ void issue_stage(
    uint32_t st, const __nv_bfloat16* __restrict__ Ahg,
    const __nv_bfloat16* __restrict__ Alg,
    const __nv_bfloat16* __restrict__ Bhg,
    const __nv_bfloat16* __restrict__ Blg,
    int brow, int bcol, int k0, int tid)
{
    {
        const __nv_bfloat16* Ag = (tid < 128) ? Ahg : Alg;
        uint32_t dst = st + ((tid < 128) ? 0u : (uint32_t)OFF_AL)
                     + (uint32_t)(tid & 127) * (LDAs * 2);
        const __nv_bfloat16* src = Ag + (size_t)(brow + (tid & 127)) * DD + k0;
        #pragma unroll
        for (int j = 0; j < 4; j++)
            cp16(dst + j * 16, src + j * 8);
    }
    #pragma unroll
    for (int j = 0; j < 4; j++) {
        int c  = tid + 256 * j;
        int c2 = c & 511;
        int kr = c2 >> 4;
        int cc = c2 & 15;
        const __nv_bfloat16* Bg = (c < 512) ? Bhg : Blg;
        uint32_t dst = st + ((c < 512) ? (uint32_t)OFF_BH : (uint32_t)OFF_BL)
                     + (uint32_t)kr * (LDBs * 2) + (uint32_t)cc * 16;
        cp16(dst, Bg + (size_t)(k0 + kr) * DD + bcol + cc * 8);
    }
}

__device__ __forceinline__ void gemm_mainloop(
    char* smraw, uint32_t sb,
    const __nv_bfloat16* __restrict__ Ahg, const __nv_bfloat16* __restrict__ Alg,
    const __nv_bfloat16* __restrict__ Bhg, const __nv_bfloat16* __restrict__ Blg,
    int brow, int bcol, int tid, int wm, int wn,
    wmma::fragment<wmma::accumulator, 16, 16, 16, float> (&acc)[2][4])
{
    #pragma unroll
    for (int i = 0; i < 2; i++)
        #pragma unroll
        for (int j = 0; j < 4; j++)
            wmma::fill_fragment(acc[i][j], 0.0f);

    issue_stage(sb, Ahg, Alg, Bhg, Blg, brow, bcol, 0, tid);
    asm volatile("cp.async.commit_group;" ::: "memory");
    issue_stage(sb + STG_BYTES, Ahg, Alg, Bhg, Blg, brow, bcol, BK, tid);
    asm volatile("cp.async.commit_group;" ::: "memory");

    for (int c = 0; c < NC; c++) {
        const int st = c % 3;
        if (c + 2 < NC) {
            issue_stage(sb + ((c + 2) % 3) * STG_BYTES, Ahg, Alg, Bhg, Blg,
                        brow, bcol, (c + 2) * BK, tid);
            asm volatile("cp.async.commit_group;" ::: "memory");
            asm volatile("cp.async.wait_group 2;" ::: "memory");
        } else if (c + 1 < NC) {
            asm volatile("cp.async.wait_group 1;" ::: "memory");
        } else {
            asm volatile("cp.async.wait_group 0;" ::: "memory");
        }
        __syncthreads();

        const __nv_bfloat16* Ah = (const __nv_bfloat16*)(smraw + st * STG_BYTES);
        const __nv_bfloat16* Al = Ah + STG_A;
        const __nv_bfloat16* Bh = Al + STG_A;
        const __nv_bfloat16* Bl = Bh + STG_B;

        #pragma unroll
        for (int ks = 0; ks < 2; ks++) {
            wmma::fragment<wmma::matrix_a, 16, 16, 16, __nv_bfloat16, wmma::row_major> ah[2], al[2];
            wmma::fragment<wmma::matrix_b, 16, 16, 16, __nv_bfloat16, wmma::row_major> bh[4], bl[4];
            #pragma unroll
            for (int i = 0; i < 2; i++) {
                wmma::load_matrix_sync(ah[i], Ah + (wm * 32 + i * 16) * LDAs + ks * 16, LDAs);
                wmma::load_matrix_sync(al[i], Al + (wm * 32 + i * 16) * LDAs + ks * 16, LDAs);
            }
            #pragma unroll
            for (int j = 0; j < 4; j++) {
                wmma::load_matrix_sync(bh[j], Bh + (ks * 16) * LDBs + wn * 64 + j * 16, LDBs);
                wmma::load_matrix_sync(bl[j], Bl + (ks * 16) * LDBs + wn * 64 + j * 16, LDBs);
            }
            #pragma unroll
            for (int i = 0; i < 2; i++)
                #pragma unroll
                for (int j = 0; j < 4; j++) {
                    wmma::mma_sync(acc[i][j], ah[i], bh[j], acc[i][j]);
                    wmma::mma_sync(acc[i][j], ah[i], bl[j], acc[i][j]);
                    wmma::mma_sync(acc[i][j], al[i], bh[j], acc[i][j]);
                }
        }
        __syncthreads();
    }
}

// ---- fused Q/K/V projection: blockIdx.z selects the problem ----
struct G3 {
    const __nv_bfloat16 *Ah[3], *Al[3], *Bh[3], *Bl[3];
    __nv_bfloat16 *Ch[3], *Cl[3];
    float alpha[3];
};

__global__ __launch_bounds__(256) void gemm_qkv(G3 g)
{
    extern __shared__ char smraw[];
    const uint32_t sb = smem_u32(smraw);
    const int tid  = threadIdx.x;
    const int wid  = tid >> 5;
    const int lane = tid & 31;
    const int wm   = wid & 3;
    const int wn   = wid >> 2;
    const int brow = blockIdx.y * 128;
    const int bcol = blockIdx.x * 128;
    const int z    = blockIdx.z;

    wmma::fragment<wmma::accumulator, 16, 16, 16, float> acc[2][4];
    gemm_mainloop(smraw, sb, g.Ah[z], g.Al[z], g.Bh[z], g.Bl[z],
                  brow, bcol, tid, wm, wn, acc);

    const float alpha = g.alpha[z];
    #pragma unroll
    for (int i = 0; i < 2; i++)
        #pragma unroll
        for (int j = 0; j < 4; j++)
            #pragma unroll
            for (int e = 0; e < acc[i][j].num_elements; e++)
                acc[i][j].x[e] *= alpha;

    // stage warp patch (32x64 fp32) in smem, then split to bf16 hi/lo
    float* ws = (float*)(smraw) + wid * 2048;
    #pragma unroll
    for (int i = 0; i < 2; i++)
        #pragma unroll
        for (int j = 0; j < 4; j++)
            wmma::store_matrix_sync(ws + i * 16 * 64 + j * 16, acc[i][j], 64, wmma::mem_row_major);
    __syncwarp();
    const float* src = ws + lane * 64;
    int grow = brow + wm * 32 + lane;
    __nv_bfloat16* chp = g.Ch[z] + (size_t)grow * DD + bcol + wn * 64;
    __nv_bfloat16* clp = g.Cl[z] + (size_t)grow * DD + bcol + wn * 64;
    #pragma unroll
    for (int gg = 0; gg < 8; gg++) {
        uint4 hv, lv;
        split2(src[8 * gg + 0], src[8 * gg + 1], hv.x, lv.x);
        split2(src[8 * gg + 2], src[8 * gg + 3], hv.y, lv.y);
        split2(src[8 * gg + 4], src[8 * gg + 5], hv.z, lv.z);
        split2(src[8 * gg + 6], src[8 * gg + 7], hv.w, lv.w);
        *(uint4*)(chp + 8 * gg) = hv;
        *(uint4*)(clp + 8 * gg) = lv;
    }
}

__global__ __launch_bounds__(256) void gemm_wo(
    const __nv_bfloat16* __restrict__ Ahg, const __nv_bfloat16* __restrict__ Alg,
    const __nv_bfloat16* __restrict__ Bhg, const __nv_bfloat16* __restrict__ Blg,
    float* __restrict__ Cf)
{
    extern __shared__ char smraw[];
    const uint32_t sb = smem_u32(smraw);
    const int tid  = threadIdx.x;
    const int wid  = tid >> 5;
    const int wm   = wid & 3;
    const int wn   = wid >> 2;
    const int brow = blockIdx.y * 128;
    const int bcol = blockIdx.x * 128;

    wmma::fragment<wmma::accumulator, 16, 16, 16, float> acc[2][4];
    gemm_mainloop(smraw, sb, Ahg, Alg, Bhg, Blg, brow, bcol, tid, wm, wn, acc);

    #pragma unroll
    for (int i = 0; i < 2; i++)
        #pragma unroll
        for (int j = 0; j < 4; j++) {
            float* Cp = Cf + (size_t)(brow + wm * 32 + i * 16) * DD + bcol + wn * 64 + j * 16;
            wmma::store_matrix_sync(Cp, acc[i][j], DD, wmma::mem_row_major);
        }
}

// ===========================================================================
// Raw-mma flash attention, q-tile 128 (2 q-blocks per warp), kv-tile 64.
// Warp (rm, cn): rows {qb*64 + rm*16} for qb in {0,1}; kv cols cn*32..+32.
// K/V fragments loaded ONCE per iter feed both q-blocks (2x mma:ldsm ratio).
// ===========================================================================
#define LQ  72
#define LSO 72
#define ATTN_SMEM (2 * 128 * LSO * 4)   // 73728 (epilogue view; >= KV view 36864)

__global__ __launch_bounds__(256, 1) void attn_mma(
    const __nv_bfloat16* __restrict__ Qhg, const __nv_bfloat16* __restrict__ Qlg,
    const __nv_bfloat16* __restrict__ Khg, const __nv_bfloat16* __restrict__ Klg,
    const __nv_bfloat16* __restrict__ Vhg, const __nv_bfloat16* __restrict__ Vlg,
    __nv_bfloat16* __restrict__ Chg, __nv_bfloat16* __restrict__ Clg)
{
    extern __shared__ char smraw[];
    __nv_bfloat16* KVs = (__nv_bfloat16*)smraw;
    __shared__ float lbuf[2][128];

    const int tid  = threadIdx.x;
    const int lane = tid & 31;
    const int wid  = tid >> 5;
    const int rm   = wid >> 1;
    const int cn   = wid & 1;
    const int q0   = blockIdx.x * 128;
    const int h    = blockIdx.y;
    const int b    = blockIdx.z;
    const int row  = tid >> 2;          // 0..63
    const int cseg = (tid & 3) * 16;
    const size_t hoff = (size_t)h * HD;

    __nv_bfloat16* Kh = KVs;
    __nv_bfloat16* Kl = KVs + 64 * LQ;
    __nv_bfloat16* Vh = KVs + 2 * 64 * LQ;
    __nv_bfloat16* Vl = KVs + 3 * 64 * LQ;

    const uint32_t base = smem_u32(KVs);
    const int rA = lane & 15, cA = (lane >> 4) * 8;
    const int rK = (lane & 7) + ((lane & 16) >> 1), cK = lane & 8;

    // ---- stage Q 128x64 hi/lo (hi spans Kh+Kl, lo spans Vh+Vl) ----------
    #pragma unroll
    for (int g = 0; g < 2; g++) {
        int rg = row + 64 * g;
        size_t gq = ((size_t)(b * SS) + q0 + rg) * DD + hoff + cseg;
        int bi = rg * LQ + cseg;
        *(uint4*)&KVs[bi]     = *(const uint4*)(Qhg + gq);
        *(uint4*)&KVs[bi + 8] = *(const uint4*)(Qhg + gq + 8);
        *(uint4*)&KVs[2 * 64 * LQ + bi]     = *(const uint4*)(Qlg + gq);
        *(uint4*)&KVs[2 * 64 * LQ + bi + 8] = *(const uint4*)(Qlg + gq + 8);
    }
    __syncthreads();

    uint32_t qh[2][4][4], ql[2][4][4];
    #pragma unroll
    for (int qb = 0; qb < 2; qb++)
        #pragma unroll
        for (int d = 0; d < 4; d++) {
            uint32_t a = base + (uint32_t)((qb * 64 + rm * 16 + rA) * LQ + d * 16 + cA) * 2;
            ldsm_x4(qh[qb][d], a);
            ldsm_x4(ql[qb][d], a + 2 * 64 * LQ * 2);
        }

    float oacc[2][8][4];
    #pragma unroll
    for (int qb = 0; qb < 2; qb++)
        #pragma unroll
        for (int n = 0; n < 8; n++)
            #pragma unroll
            for (int e = 0; e < 4; e++) oacc[qb][n][e] = 0.0f;
    float ls[2][2] = {{0.0f, 0.0f}, {0.0f, 0.0f}};

    for (int kv0 = 0; kv0 < SS; kv0 += 64) {
        __syncthreads();

        // ---- load K,V hi/lo tiles (pre-split bf16) --------------------
        {
            const size_t kb = ((size_t)(b * SS) + kv0 + row) * DD + hoff + cseg;
            int bi = row * LQ + cseg;
            *(uint4*)&Kh[bi]     = *(const uint4*)(Khg + kb);
            *(uint4*)&Kh[bi + 8] = *(const uint4*)(Khg + kb + 8);
            *(uint4*)&Kl[bi]     = *(const uint4*)(Klg + kb);
            *(uint4*)&Kl[bi + 8] = *(const uint4*)(Klg + kb + 8);
            *(uint4*)&Vh[bi]     = *(const uint4*)(Vhg + kb);
            *(uint4*)&Vh[bi + 8] = *(const uint4*)(Vhg + kb + 8);
            *(uint4*)&Vl[bi]     = *(const uint4*)(Vlg + kb);
            *(uint4*)&Vl[bi + 8] = *(const uint4*)(Vlg + kb + 8);
        }
        __syncthreads();

        // ---- S = Q @ K^T (3-term), K frags shared across both q-blocks --
        float s[2][4][4];
        #pragma unroll
        for (int qb = 0; qb < 2; qb++)
            #pragma unroll
            for (int j = 0; j < 4; j++)
                #pragma unroll
                for (int e = 0; e < 4; e++) s[qb][j][e] = 0.0f;

        #pragma unroll
        for (int d = 0; d < 4; d++) {
            #pragma unroll
            for (int jp = 0; jp < 2; jp++) {
                uint32_t kh[4], kl[4];
                uint32_t a = base + (uint32_t)((cn * 32 + jp * 16 + rK) * LQ + d * 16 + cK) * 2;
                ldsm_x4(kh, a);
                ldsm_x4(kl, a + 64 * LQ * 2);
                #pragma unroll
                for (int qb = 0; qb < 2; qb++) {
                    mma16816(s[qb][jp * 2],     qh[qb][d], kh[0], kh[1]);
                    mma16816(s[qb][jp * 2],     ql[qb][d], kh[0], kh[1]);
                    mma16816(s[qb][jp * 2],     qh[qb][d], kl[0], kl[1]);
                    mma16816(s[qb][jp * 2 + 1], qh[qb][d], kh[2], kh[3]);
                    mma16816(s[qb][jp * 2 + 1], ql[qb][d], kh[2], kh[3]);
                    mma16816(s[qb][jp * 2 + 1], qh[qb][d], kl[2], kl[3]);
                }
            }
        }

        // ---- exp + row-sum + repack P (register-only) --------------------
        uint32_t ph[2][2][4], pl[2][2][4];
        #pragma unroll
        for (int qb = 0; qb < 2; qb++) {
            #pragma unroll
            for (int j = 0; j < 4; j++) {
                s[qb][j][0] = __expf(s[qb][j][0]); s[qb][j][1] = __expf(s[qb][j][1]);
                s[qb][j][2] = __expf(s[qb][j][2]); s[qb][j][3] = __expf(s[qb][j][3]);
                ls[qb][0] += s[qb][j][0] + s[qb][j][1];
                ls[qb][1] += s[qb][j][2] + s[qb][j][3];
            }
            #pragma unroll
            for (int kk = 0; kk < 2; kk++) {
                int j0 = kk * 2;
                split2(s[qb][j0][0],     s[qb][j0][1],     ph[qb][kk][0], pl[qb][kk][0]);
                split2(s[qb][j0][2],     s[qb][j0][3],     ph[qb][kk][1], pl[qb][kk][1]);
                split2(s[qb][j0 + 1][0], s[qb][j0 + 1][1], ph[qb][kk][2], pl[qb][kk][2]);
                split2(s[qb][j0 + 1][2], s[qb][j0 + 1][3], ph[qb][kk][3], pl[qb][kk][3]);
            }
        }

        // ---- O += P @ V (3-term), V frags shared across both q-blocks ----
        #pragma unroll
        for (int kk = 0; kk < 2; kk++) {
            #pragma unroll
            for (int np = 0; np < 4; np++) {
                uint32_t vh[4], vl[4];
                uint32_t a = base + (uint32_t)(2 * 64 * LQ + (cn * 32 + kk * 16 + rA) * LQ + np * 16 + cA) * 2;
                ldsm_x4_t(vh, a);
                ldsm_x4_t(vl, a + 64 * LQ * 2);
                #pragma unroll
                for (int qb = 0; qb < 2; qb++) {
                    mma16816(oacc[qb][np * 2],     ph[qb][kk], vh[0], vh[1]);
                    mma16816(oacc[qb][np * 2],     pl[qb][kk], vh[0], vh[1]);
                    mma16816(oacc[qb][np * 2],     ph[qb][kk], vl[0], vl[1]);
                    mma16816(oacc[qb][np * 2 + 1], ph[qb][kk], vh[2], vh[3]);
                    mma16816(oacc[qb][np * 2 + 1], pl[qb][kk], vh[2], vh[3]);
                    mma16816(oacc[qb][np * 2 + 1], ph[qb][kk], vl[2], vl[3]);
                }
            }
        }
    }

    // ---- row-sum halves ------------------------------------------------
    #pragma unroll
    for (int qb = 0; qb < 2; qb++) {
        float a0 = ls[qb][0], a1 = ls[qb][1];
        a0 += __shfl_xor_sync(0xffffffffu, a0, 1);
        a0 += __shfl_xor_sync(0xffffffffu, a0, 2);
        a1 += __shfl_xor_sync(0xffffffffu, a1, 1);
        a1 += __shfl_xor_sync(0xffffffffu, a1, 2);
        if ((lane & 3) == 0) {
            lbuf[cn][qb * 64 + rm * 16 + (lane >> 2)]     = a0;
            lbuf[cn][qb * 64 + rm * 16 + (lane >> 2) + 8] = a1;
        }
    }

    __syncthreads();   // KV reads done before aliasing as obuf

    // ---- merge O partials through smem ----------------------------------
    float* obuf = (float*)smraw;   // [2][128][LSO]
    {
        int c0 = (lane & 3) * 2;
        float* ob = obuf + cn * 128 * LSO;
        #pragma unroll
        for (int qb = 0; qb < 2; qb++) {
            int r0 = qb * 64 + rm * 16 + (lane >> 2);
            #pragma unroll
            for (int n = 0; n < 8; n++) {
                float2 lo; lo.x = oacc[qb][n][0]; lo.y = oacc[qb][n][1];
                float2 hi; hi.x = oacc[qb][n][2]; hi.y = oacc[qb][n][3];
                *(float2*)&ob[r0 * LSO + n * 8 + c0]       = lo;
                *(float2*)&ob[(r0 + 8) * LSO + n * 8 + c0] = hi;
            }
        }
    }
    __syncthreads();

    // ---- normalize + split-write ctx hi/lo --------------------------------
    #pragma unroll
    for (int g = 0; g < 2; g++) {
        int rg = row + 64 * g;
        const float inv = 1.0f / (lbuf[0][rg] + lbuf[1][rg]);
        size_t gq = ((size_t)(b * SS) + q0 + rg) * DD + hoff + cseg;
        __nv_bfloat16* chp = Chg + gq;
        __nv_bfloat16* clp = Clg + gq;
        #pragma unroll
        for (int gg = 0; gg < 2; gg++) {
            float v[8];
            #pragma unroll
            for (int e = 0; e < 8; e++) {
                int cc = cseg + gg * 8 + e;
                v[e] = (obuf[rg * LSO + cc] + obuf[128 * LSO + rg * LSO + cc]) * inv;
            }
            uint4 hv, lv;
            split2(v[0], v[1], hv.x, lv.x);
            split2(v[2], v[3], hv.y, lv.y);
            split2(v[4], v[5], hv.z, lv.z);
            split2(v[6], v[7], hv.w, lv.w);
            *(uint4*)(chp + gg * 8) = hv;
            *(uint4*)(clp + gg * 8) = lv;
        }
    }
}

// ---------------------------------------------------------------------------
extern "C" void kernel_launch(void* const* d_in, const int* in_sizes, int n_in,
                              void* d_out, int out_size)
{
    const float* queries = (const float*)d_in[0];
    const float* keys    = (const float*)d_in[1];
    const float* values  = (const float*)d_in[2];
    const float* Wq      = (const float*)d_in[3];
    const float* Wk      = (const float*)d_in[4];
    const float* Wv      = (const float*)d_in[5];
    const float* Wo      = (const float*)d_in[6];
    float* out = (float*)d_out;

    __nv_bfloat16 *iqh,*iql,*ikh,*ikl,*ivh,*ivl;
    __nv_bfloat16 *wqh,*wql,*wkh,*wkl,*wvh,*wvl,*woh,*wol;
    __nv_bfloat16 *Qh,*Ql,*Kh,*Kl,*Vh,*Vl,*Ch,*Cl;
    cudaGetSymbolAddress((void**)&iqh, g_iqh); cudaGetSymbolAddress((void**)&iql, g_iql);
    cudaGetSymbolAddress((void**)&ikh, g_ikh); cudaGetSymbolAddress((void**)&ikl, g_ikl);
    cudaGetSymbolAddress((void**)&ivh, g_ivh); cudaGetSymbolAddress((void**)&ivl, g_ivl);
    cudaGetSymbolAddress((void**)&wqh, g_wqh); cudaGetSymbolAddress((void**)&wql, g_wql);
    cudaGetSymbolAddress((void**)&wkh, g_wkh); cudaGetSymbolAddress((void**)&wkl, g_wkl);
    cudaGetSymbolAddress((void**)&wvh, g_wvh); cudaGetSymbolAddress((void**)&wvl, g_wvl);
    cudaGetSymbolAddress((void**)&woh, g_woh); cudaGetSymbolAddress((void**)&wol, g_wol);
    cudaGetSymbolAddress((void**)&Qh, g_Qh); cudaGetSymbolAddress((void**)&Ql, g_Ql);
    cudaGetSymbolAddress((void**)&Kh, g_Kh); cudaGetSymbolAddress((void**)&Kl, g_Kl);
    cudaGetSymbolAddress((void**)&Vh, g_Vh); cudaGetSymbolAddress((void**)&Vl, g_Vl);
    cudaGetSymbolAddress((void**)&Ch, g_Ch); cudaGetSymbolAddress((void**)&Cl, g_Cl);

    cudaFuncSetAttribute(gemm_qkv, cudaFuncAttributeMaxDynamicSharedMemorySize, GEMM_SMEM);
    cudaFuncSetAttribute(gemm_wo,  cudaFuncAttributeMaxDynamicSharedMemorySize, GEMM_SMEM);
    cudaFuncSetAttribute(attn_mma, cudaFuncAttributeMaxDynamicSharedMemorySize, ATTN_SMEM);

    // ---- splits ----
    split_k<<<NELEM / 4 / 256, 256>>>(queries, iqh, iql, NELEM / 4);
    split_k<<<NELEM / 4 / 256, 256>>>(keys,    ikh, ikl, NELEM / 4);
    split_k<<<NELEM / 4 / 256, 256>>>(values,  ivh, ivl, NELEM / 4);
    split_k<<<WELEM / 4 / 256, 256>>>(Wq, wqh, wql, WELEM / 4);
    split_k<<<WELEM / 4 / 256, 256>>>(Wk, wkh, wkl, WELEM / 4);
    split_k<<<WELEM / 4 / 256, 256>>>(Wv, wvh, wvl, WELEM / 4);
    split_k<<<WELEM / 4 / 256, 256>>>(Wo, woh, wol, WELEM / 4);

    // ---- fused QKV projection ----
    G3 g;
    g.Ah[0] = iqh; g.Al[0] = iql; g.Bh[0] = wqh; g.Bl[0] = wql; g.Ch[0] = Qh; g.Cl[0] = Ql; g.alpha[0] = 0.125f;
    g.Ah[1] = ikh; g.Al[1] = ikl; g.Bh[1] = wkh; g.Bl[1] = wkl; g.Ch[1] = Kh; g.Cl[1] = Kl; g.alpha[1] = 1.0f;
    g.Ah[2] = ivh; g.Al[2] = ivl; g.Bh[2] = wvh; g.Bl[2] = wvl; g.Ch[2] = Vh; g.Cl[2] = Vl; g.alpha[2] = 1.0f;

    gemm_qkv<<<dim3(DD / 128, MROWS / 128, 3), 256, GEMM_SMEM>>>(g);

    attn_mma<<<dim3(SS / 128, HH, BB), 256, ATTN_SMEM>>>(Qh, Ql, Kh, Kl, Vh, Vl, Ch, Cl);

    gemm_wo<<<dim3(DD / 128, MROWS / 128), 256, GEMM_SMEM>>>(Ch, Cl, woh, wol, out);
}

// round 12
// speedup vs baseline: 1.0432x; 1.0432x over previous
#include <cuda_runtime.h>
#include <cuda_bf16.h>
#include <mma.h>
#include <math.h>
#include <stdint.h>

using namespace nvcuda;

// Problem constants
#define BB 2
#define SS 2048
#define DD 1024
#define HH 16
#define HD 64
#define MROWS (BB*SS)      // 4096
#define NELEM (BB*SS*DD)   // 4M
#define WELEM (DD*DD)      // 1M

// ---------------------------------------------------------------------------
// Global scratch (allocation-free rule: __device__ globals), all bf16 hi/lo
// ---------------------------------------------------------------------------
__device__ __nv_bfloat16 g_iqh[NELEM], g_iql[NELEM];
__device__ __nv_bfloat16 g_ikh[NELEM], g_ikl[NELEM];
__device__ __nv_bfloat16 g_ivh[NELEM], g_ivl[NELEM];
__device__ __nv_bfloat16 g_wqh[WELEM], g_wql[WELEM];
__device__ __nv_bfloat16 g_wkh[WELEM], g_wkl[WELEM];
__device__ __nv_bfloat16 g_wvh[WELEM], g_wvl[WELEM];
__device__ __nv_bfloat16 g_woh[WELEM], g_wol[WELEM];
__device__ __nv_bfloat16 g_Qh[NELEM], g_Ql[NELEM];
__device__ __nv_bfloat16 g_Kh[NELEM], g_Kl[NELEM];
__device__ __nv_bfloat16 g_Vh[NELEM], g_Vl[NELEM];
__device__ __nv_bfloat16 g_Ch[NELEM], g_Cl[NELEM];

__device__ __forceinline__ void bsplit4(float4 v, uint2& h, uint2& l) {
    __nv_bfloat162 h0, h1, l0, l1;
    h0.x = __float2bfloat16(v.x); h0.y = __float2bfloat16(v.y);
    h1.x = __float2bfloat16(v.z); h1.y = __float2bfloat16(v.w);
    l0.x = __float2bfloat16(v.x - __bfloat162float(h0.x));
    l0.y = __float2bfloat16(v.y - __bfloat162float(h0.y));
    l1.x = __float2bfloat16(v.z - __bfloat162float(h1.x));
    l1.y = __float2bfloat16(v.w - __bfloat162float(h1.y));
    h.x = *(uint32_t*)&h0; h.y = *(uint32_t*)&h1;
    l.x = *(uint32_t*)&l0; l.y = *(uint32_t*)&l1;
}

__device__ __forceinline__ void split2(float x, float y, uint32_t& hi, uint32_t& lo) {
    uint32_t h;
    asm("cvt.rn.bf16x2.f32 %0, %1, %2;" : "=r"(h) : "f"(y), "f"(x));
    float hx = __uint_as_float(h << 16);
    float hy = __uint_as_float(h & 0xffff0000u);
    uint32_t l;
    asm("cvt.rn.bf16x2.f32 %0, %1, %2;" : "=r"(l) : "f"(y - hy), "f"(x - hx));
    hi = h; lo = l;
}

__device__ __forceinline__ uint32_t smem_u32(const void* p) {
    uint32_t a;
    asm("{ .reg .u64 t; cvta.to.shared.u64 t, %1; cvt.u32.u64 %0, t; }"
        : "=r"(a) : "l"(p));
    return a;
}
__device__ __forceinline__ void cp16(uint32_t dst, const void* src) {
    asm volatile("cp.async.cg.shared.global [%0], [%1], 16;" :: "r"(dst), "l"(src));
}
__device__ __forceinline__ void ldsm_x4(uint32_t* r, uint32_t addr) {
    asm volatile("ldmatrix.sync.aligned.m8n8.x4.shared.b16 {%0,%1,%2,%3}, [%4];"
        : "=r"(r[0]), "=r"(r[1]), "=r"(r[2]), "=r"(r[3]) : "r"(addr));
}
__device__ __forceinline__ void ldsm_x4_t(uint32_t* r, uint32_t addr) {
    asm volatile("ldmatrix.sync.aligned.m8n8.x4.trans.shared.b16 {%0,%1,%2,%3}, [%4];"
        : "=r"(r[0]), "=r"(r[1]), "=r"(r[2]), "=r"(r[3]) : "r"(addr));
}
__device__ __forceinline__ void mma16816(float* c, const uint32_t* a, uint32_t b0, uint32_t b1) {
    asm volatile(
        "mma.sync.aligned.m16n8k16.row.col.f32.bf16.bf16.f32 "
        "{%0,%1,%2,%3}, {%4,%5,%6,%7}, {%8,%9}, {%0,%1,%2,%3};"
        : "+f"(c[0]), "+f"(c[1]), "+f"(c[2]), "+f"(c[3])
        : "r"(a[0]), "r"(a[1]), "r"(a[2]), "r"(a[3]), "r"(b0), "r"(b1));
}

// ===========================================================================
// Split kernel: fp32 -> bf16 hi/lo, vectorized.
// ===========================================================================
__global__ __launch_bounds__(256) void split_k(
    const float* __restrict__ x, __nv_bfloat16* __restrict__ h,
    __nv_bfloat16* __restrict__ l, int n4)
{
    int i = blockIdx.x * blockDim.x + threadIdx.x;
    if (i < n4) {
        float4 v = ((const float4*)x)[i];
        uint2 hh, ll;
        bsplit4(v, hh, ll);
        ((uint2*)h)[i] = hh;
        ((uint2*)l)[i] = ll;
    }
}

// ===========================================================================
// GEMM mainloop — round-10 proven config: 2-stage cp.async, 75.7 KB smem
// (2 CTAs/SM), 128x128 tile, BK=32, 8 warps (4x2), warp tile 32x64.
// ===========================================================================
#define BK 32
#define NC (DD / BK)       // 32
#define LDAs 40
#define LDBs 136
#define STG_A (128 * LDAs)
#define STG_B (BK * LDBs)
#define OFF_AL (STG_A * 2)
#define OFF_BH (2 * STG_A * 2)
#define OFF_BL (2 * STG_A * 2 + STG_B * 2)
#define STG_BYTES ((2 * STG_A + 2 * STG_B) * 2)   // 37888
#define GEMM_SMEM (2 * STG_BYTES)                  // 75776

__device__ __forceinline__ void issue_stage(
    uint32_t st, const __nv_bfloat16* __restrict__ Ahg,
    const __nv_bfloat16* __restrict__ Alg,
    const __nv_bfloat16* __restrict__ Bhg,
    const __nv_bfloat16* __restrict__ Blg,
    int brow, int bcol, int k0, int tid)
{
    {
        const __nv_bfloat16* Ag = (tid < 128) ? Ahg : Alg;
        uint32_t dst = st + ((tid < 128) ? 0u : (uint32_t)OFF_AL)
                     + (uint32_t)(tid & 127) * (LDAs * 2);
        const __nv_bfloat16* src = Ag + (size_t)(brow + (tid & 127)) * DD + k0;
        #pragma unroll
        for (int j = 0; j < 4; j++)
            cp16(dst + j * 16, src + j * 8);
    }
    #pragma unroll
    for (int j = 0; j < 4; j++) {
        int c  = tid + 256 * j;
        int c2 = c & 511;
        int kr = c2 >> 4;
        int cc = c2 & 15;
        const __nv_bfloat16* Bg = (c < 512) ? Bhg : Blg;
        uint32_t dst = st + ((c < 512) ? (uint32_t)OFF_BH : (uint32_t)OFF_BL)
                     + (uint32_t)kr * (LDBs * 2) + (uint32_t)cc * 16;
        cp16(dst, Bg + (size_t)(k0 + kr) * DD + bcol + cc * 8);
    }
}

__device__ __forceinline__ void gemm_mainloop(
    char* smraw, uint32_t sb,
    const __nv_bfloat16* __restrict__ Ahg, const __nv_bfloat16* __restrict__ Alg,
    const __nv_bfloat16* __restrict__ Bhg, const __nv_bfloat16* __restrict__ Blg,
    int brow, int bcol, int tid, int wm, int wn,
    wmma::fragment<wmma::accumulator, 16, 16, 16, float> (&acc)[2][4])
{
    #pragma unroll
    for (int i = 0; i < 2; i++)
        #pragma unroll
        for (int j = 0; j < 4; j++)
            wmma::fill_fragment(acc[i][j], 0.0f);

    issue_stage(sb, Ahg, Alg, Bhg, Blg, brow, bcol, 0, tid);
    asm volatile("cp.async.commit_group;" ::: "memory");

    for (int c = 0; c < NC; c++) {
        const int st = c & 1;
        if (c + 1 < NC) {
            issue_stage(sb + (st ^ 1) * STG_BYTES, Ahg, Alg, Bhg, Blg,
                        brow, bcol, (c + 1) * BK, tid);
            asm volatile("cp.async.commit_group;" ::: "memory");
            asm volatile("cp.async.wait_group 1;" ::: "memory");
        } else {
            asm volatile("cp.async.wait_group 0;" ::: "memory");
        }
        __syncthreads();

        const __nv_bfloat16* Ah = (const __nv_bfloat16*)(smraw + st * STG_BYTES);
        const __nv_bfloat16* Al = Ah + STG_A;
        const __nv_bfloat16* Bh = Al + STG_A;
        const __nv_bfloat16* Bl = Bh + STG_B;

        #pragma unroll
        for (int ks = 0; ks < 2; ks++) {
            wmma::fragment<wmma::matrix_a, 16, 16, 16, __nv_bfloat16, wmma::row_major> ah[2], al[2];
            wmma::fragment<wmma::matrix_b, 16, 16, 16, __nv_bfloat16, wmma::row_major> bh[4], bl[4];
            #pragma unroll
            for (int i = 0; i < 2; i++) {
                wmma::load_matrix_sync(ah[i], Ah + (wm * 32 + i * 16) * LDAs + ks * 16, LDAs);
                wmma::load_matrix_sync(al[i], Al + (wm * 32 + i * 16) * LDAs + ks * 16, LDAs);
            }
            #pragma unroll
            for (int j = 0; j < 4; j++) {
                wmma::load_matrix_sync(bh[j], Bh + (ks * 16) * LDBs + wn * 64 + j * 16, LDBs);
                wmma::load_matrix_sync(bl[j], Bl + (ks * 16) * LDBs + wn * 64 + j * 16, LDBs);
            }
            #pragma unroll
            for (int i = 0; i < 2; i++)
                #pragma unroll
                for (int j = 0; j < 4; j++) {
                    wmma::mma_sync(acc[i][j], ah[i], bh[j], acc[i][j]);
                    wmma::mma_sync(acc[i][j], ah[i], bl[j], acc[i][j]);
                    wmma::mma_sync(acc[i][j], al[i], bh[j], acc[i][j]);
                }
        }
        __syncthreads();
    }
}

// ---- fused Q/K/V projection: blockIdx.z selects the problem ----
struct G3 {
    const __nv_bfloat16 *Ah[3], *Al[3], *Bh[3], *Bl[3];
    __nv_bfloat16 *Ch[3], *Cl[3];
    float alpha[3];
};

__global__ __launch_bounds__(256) void gemm_qkv(G3 g)
{
    extern __shared__ char smraw[];
    const uint32_t sb = smem_u32(smraw);
    const int tid  = threadIdx.x;
    const int wid  = tid >> 5;
    const int lane = tid & 31;
    const int wm   = wid & 3;
    const int wn   = wid >> 2;
    const int brow = blockIdx.y * 128;
    const int bcol = blockIdx.x * 128;
    const int z    = blockIdx.z;

    wmma::fragment<wmma::accumulator, 16, 16, 16, float> acc[2][4];
    gemm_mainloop(smraw, sb, g.Ah[z], g.Al[z], g.Bh[z], g.Bl[z],
                  brow, bcol, tid, wm, wn, acc);

    const float alpha = g.alpha[z];
    #pragma unroll
    for (int i = 0; i < 2; i++)
        #pragma unroll
        for (int j = 0; j < 4; j++)
            #pragma unroll
            for (int e = 0; e < acc[i][j].num_elements; e++)
                acc[i][j].x[e] *= alpha;

    // stage warp patch (32x64 fp32) in smem, then split to bf16 hi/lo
    float* ws = (float*)(smraw) + wid * 2048;
    #pragma unroll
    for (int i = 0; i < 2; i++)
        #pragma unroll
        for (int j = 0; j < 4; j++)
            wmma::store_matrix_sync(ws + i * 16 * 64 + j * 16, acc[i][j], 64, wmma::mem_row_major);
    __syncwarp();
    const float* src = ws + lane * 64;
    int grow = brow + wm * 32 + lane;
    __nv_bfloat16* chp = g.Ch[z] + (size_t)grow * DD + bcol + wn * 64;
    __nv_bfloat16* clp = g.Cl[z] + (size_t)grow * DD + bcol + wn * 64;
    #pragma unroll
    for (int gg = 0; gg < 8; gg++) {
        uint4 hv, lv;
        split2(src[8 * gg + 0], src[8 * gg + 1], hv.x, lv.x);
        split2(src[8 * gg + 2], src[8 * gg + 3], hv.y, lv.y);
        split2(src[8 * gg + 4], src[8 * gg + 5], hv.z, lv.z);
        split2(src[8 * gg + 6], src[8 * gg + 7], hv.w, lv.w);
        *(uint4*)(chp + 8 * gg) = hv;
        *(uint4*)(clp + 8 * gg) = lv;
    }
}

__global__ __launch_bounds__(256) void gemm_wo(
    const __nv_bfloat16* __restrict__ Ahg, const __nv_bfloat16* __restrict__ Alg,
    const __nv_bfloat16* __restrict__ Bhg, const __nv_bfloat16* __restrict__ Blg,
    float* __restrict__ Cf)
{
    extern __shared__ char smraw[];
    const uint32_t sb = smem_u32(smraw);
    const int tid  = threadIdx.x;
    const int wid  = tid >> 5;
    const int wm   = wid & 3;
    const int wn   = wid >> 2;
    const int brow = blockIdx.y * 128;
    const int bcol = blockIdx.x * 128;

    wmma::fragment<wmma::accumulator, 16, 16, 16, float> acc[2][4];
    gemm_mainloop(smraw, sb, Ahg, Alg, Bhg, Blg, brow, bcol, tid, wm, wn, acc);

    #pragma unroll
    for (int i = 0; i < 2; i++)
        #pragma unroll
        for (int j = 0; j < 4; j++) {
            float* Cp = Cf + (size_t)(brow + wm * 32 + i * 16) * DD + bcol + wn * 64 + j * 16;
            wmma::store_matrix_sync(Cp, acc[i][j], DD, wmma::mem_row_major);
        }
}

// ===========================================================================
// Raw-mma flash attention, q-tile 64 (round-10 shape), DOUBLE-BUFFERED
// cp.async KV staging: prefetch tile c+1 while computing tile c.
// ===========================================================================
#define LQ  72
#define LSO 72
#define KVB (4 * 64 * LQ)                    // bf16 elems per buffer (36864 B)
#define ATTN_SMEM (2 * KVB * 2)              // 73728

__global__ __launch_bounds__(256, 2) void attn_mma(
    const __nv_bfloat16* __restrict__ Qhg, const __nv_bfloat16* __restrict__ Qlg,
    const __nv_bfloat16* __restrict__ Khg, const __nv_bfloat16* __restrict__ Klg,
    const __nv_bfloat16* __restrict__ Vhg, const __nv_bfloat16* __restrict__ Vlg,
    __nv_bfloat16* __restrict__ Chg, __nv_bfloat16* __restrict__ Clg)
{
    extern __shared__ char smraw[];
    __nv_bfloat16* KVs = (__nv_bfloat16*)smraw;
    __shared__ float lbuf[2][64];

    const int tid  = threadIdx.x;
    const int lane = tid & 31;
    const int wid  = tid >> 5;
    const int rm   = wid >> 1;
    const int cn   = wid & 1;
    const int q0   = blockIdx.x * 64;
    const int h    = blockIdx.y;
    const int b    = blockIdx.z;
    const int row  = tid >> 2;
    const int cseg = (tid & 3) * 16;
    const size_t hoff = (size_t)h * HD;
    const size_t gbase = ((size_t)(b * SS) + q0 + row) * DD + hoff + cseg;

    const uint32_t base = smem_u32(KVs);
    const int rA = lane & 15, cA = (lane >> 4) * 8;
    const int rK = (lane & 7) + ((lane & 16) >> 1), cK = lane & 8;

    // ---- stage Q in buffer 0's V region, hoist A-fragments --------------
    {
        int bi = row * LQ + cseg;
        *(uint4*)&KVs[2 * 64 * LQ + bi]     = *(const uint4*)(Qhg + gbase);
        *(uint4*)&KVs[2 * 64 * LQ + bi + 8] = *(const uint4*)(Qhg + gbase + 8);
        *(uint4*)&KVs[3 * 64 * LQ + bi]     = *(const uint4*)(Qlg + gbase);
        *(uint4*)&KVs[3 * 64 * LQ + bi + 8] = *(const uint4*)(Qlg + gbase + 8);
    }
    __syncthreads();

    uint32_t qh[4][4], ql[4][4];
    #pragma unroll
    for (int d = 0; d < 4; d++) {
        uint32_t a = base + (uint32_t)(2 * 64 * LQ + (rm * 16 + rA) * LQ + d * 16 + cA) * 2;
        ldsm_x4(qh[d], a);
        ldsm_x4(ql[d], a + 64 * LQ * 2);
    }
    __syncthreads();   // Q frag loads complete before cp.async overwrites buf0

    // KV tile issue for buffer `buf`, kv offset kv0 (8x cp16 per thread)
    auto issue_kv = [&](int buf, int kv0) {
        const size_t kb = ((size_t)(b * SS) + kv0 + row) * DD + hoff + cseg;
        uint32_t bb = base + (uint32_t)buf * (KVB * 2)
                    + (uint32_t)(row * LQ + cseg) * 2;
        cp16(bb,                      Khg + kb);
        cp16(bb + 16,                 Khg + kb + 8);
        cp16(bb + 64 * LQ * 2,        Klg + kb);
        cp16(bb + 64 * LQ * 2 + 16,   Klg + kb + 8);
        cp16(bb + 2 * 64 * LQ * 2,      Vhg + kb);
        cp16(bb + 2 * 64 * LQ * 2 + 16, Vhg + kb + 8);
        cp16(bb + 3 * 64 * LQ * 2,      Vlg + kb);
        cp16(bb + 3 * 64 * LQ * 2 + 16, Vlg + kb + 8);
    };

    issue_kv(0, 0);
    asm volatile("cp.async.commit_group;" ::: "memory");

    float oacc[8][4];
    #pragma unroll
    for (int n = 0; n < 8; n++)
        #pragma unroll
        for (int e = 0; e < 4; e++) oacc[n][e] = 0.0f;
    float ls0 = 0.0f, ls1 = 0.0f;

    for (int c = 0; c < SS / 64; c++) {
        if (c + 1 < SS / 64) {
            issue_kv((c + 1) & 1, (c + 1) * 64);
            asm volatile("cp.async.commit_group;" ::: "memory");
            asm volatile("cp.async.wait_group 1;" ::: "memory");
        } else {
            asm volatile("cp.async.wait_group 0;" ::: "memory");
        }
        __syncthreads();

        const uint32_t bb = base + (uint32_t)(c & 1) * (KVB * 2);

        // ---- S = Q @ K^T (3-term) --------------------------------------
        float s[4][4];
        #pragma unroll
        for (int j = 0; j < 4; j++)
            #pragma unroll
            for (int e = 0; e < 4; e++) s[j][e] = 0.0f;

        #pragma unroll
        for (int d = 0; d < 4; d++) {
            #pragma unroll
            for (int jp = 0; jp < 2; jp++) {
                uint32_t kh[4], kl[4];
                uint32_t a = bb + (uint32_t)((cn * 32 + jp * 16 + rK) * LQ + d * 16 + cK) * 2;
                ldsm_x4(kh, a);
                ldsm_x4(kl, a + 64 * LQ * 2);
                mma16816(s[jp * 2],     qh[d], kh[0], kh[1]);
                mma16816(s[jp * 2],     ql[d], kh[0], kh[1]);
                mma16816(s[jp * 2],     qh[d], kl[0], kl[1]);
                mma16816(s[jp * 2 + 1], qh[d], kh[2], kh[3]);
                mma16816(s[jp * 2 + 1], ql[d], kh[2], kh[3]);
                mma16816(s[jp * 2 + 1], qh[d], kl[2], kl[3]);
            }
        }

        // ---- exp + row-sum ----------------------------------------------
        #pragma unroll
        for (int j = 0; j < 4; j++) {
            s[j][0] = __expf(s[j][0]); s[j][1] = __expf(s[j][1]);
            s[j][2] = __expf(s[j][2]); s[j][3] = __expf(s[j][3]);
            ls0 += s[j][0] + s[j][1];
            ls1 += s[j][2] + s[j][3];
        }

        // ---- repack P -> A fragments (register-only) ----------------------
        uint32_t ph[2][4], pl[2][4];
        #pragma unroll
        for (int kk = 0; kk < 2; kk++) {
            int j0 = kk * 2;
            split2(s[j0][0],     s[j0][1],     ph[kk][0], pl[kk][0]);
            split2(s[j0][2],     s[j0][3],     ph[kk][1], pl[kk][1]);
            split2(s[j0 + 1][0], s[j0 + 1][1], ph[kk][2], pl[kk][2]);
            split2(s[j0 + 1][2], s[j0 + 1][3], ph[kk][3], pl[kk][3]);
        }

        // ---- O_partial += P @ V (3-term) ----------------------------------
        #pragma unroll
        for (int kk = 0; kk < 2; kk++) {
            #pragma unroll
            for (int np = 0; np < 4; np++) {
                uint32_t vh[4], vl[4];
                uint32_t a = bb + (uint32_t)(2 * 64 * LQ + (cn * 32 + kk * 16 + rA) * LQ + np * 16 + cA) * 2;
                ldsm_x4_t(vh, a);
                ldsm_x4_t(vl, a + 64 * LQ * 2);
                mma16816(oacc[np * 2],     ph[kk], vh[0], vh[1]);
                mma16816(oacc[np * 2],     pl[kk], vh[0], vh[1]);
                mma16816(oacc[np * 2],     ph[kk], vl[0], vl[1]);
                mma16816(oacc[np * 2 + 1], ph[kk], vh[2], vh[3]);
                mma16816(oacc[np * 2 + 1], pl[kk], vh[2], vh[3]);
                mma16816(oacc[np * 2 + 1], ph[kk], vl[2], vl[3]);
            }
        }
        __syncthreads();   // reads of buf (c&1) done before iter c+1 writes it
    }

    // ---- row-sum halves ----------------------------------------------------
    ls0 += __shfl_xor_sync(0xffffffffu, ls0, 1);
    ls0 += __shfl_xor_sync(0xffffffffu, ls0, 2);
    ls1 += __shfl_xor_sync(0xffffffffu, ls1, 1);
    ls1 += __shfl_xor_sync(0xffffffffu, ls1, 2);
    if ((lane & 3) == 0) {
        lbuf[cn][rm * 16 + (lane >> 2)]     = ls0;
        lbuf[cn][rm * 16 + (lane >> 2) + 8] = ls1;
    }
    __syncthreads();

    // ---- merge O partials through smem (aliased over KV buffers) -----------
    float* obuf = (float*)smraw;   // [2][64][LSO] = 36864 B each half
    {
        int r0 = rm * 16 + (lane >> 2);
        int c0 = (lane & 3) * 2;
        float* ob = obuf + cn * 64 * LSO;
        #pragma unroll
        for (int n = 0; n < 8; n++) {
            float2 lo; lo.x = oacc[n][0]; lo.y = oacc[n][1];
            float2 hi; hi.x = oacc[n][2]; hi.y = oacc[n][3];
            *(float2*)&ob[r0 * LSO + n * 8 + c0]       = lo;
            *(float2*)&ob[(r0 + 8) * LSO + n * 8 + c0] = hi;
        }
    }
    __syncthreads();

    // ---- normalize + split-write ctx hi/lo -----------------------------------
    {
        const float inv = 1.0f / (lbuf[0][row] + lbuf[1][row]);
        __nv_bfloat16* chp = Chg + gbase;
        __nv_bfloat16* clp = Clg + gbase;
        #pragma unroll
        for (int g = 0; g < 2; g++) {
            float v[8];
            #pragma unroll
            for (int e = 0; e < 8; e++) {
                int cc = cseg + g * 8 + e;
                v[e] = (obuf[row * LSO + cc] + obuf[64 * LSO + row * LSO + cc]) * inv;
            }
            uint4 hv, lv;
            split2(v[0], v[1], hv.x, lv.x);
            split2(v[2], v[3], hv.y, lv.y);
            split2(v[4], v[5], hv.z, lv.z);
            split2(v[6], v[7], hv.w, lv.w);
            *(uint4*)(chp + g * 8) = hv;
            *(uint4*)(clp + g * 8) = lv;
        }
    }
}

// ---------------------------------------------------------------------------
extern "C" void kernel_launch(void* const* d_in, const int* in_sizes, int n_in,
                              void* d_out, int out_size)
{
    const float* queries = (const float*)d_in[0];
    const float* keys    = (const float*)d_in[1];
    const float* values  = (const float*)d_in[2];
    const float* Wq      = (const float*)d_in[3];
    const float* Wk      = (const float*)d_in[4];
    const float* Wv      = (const float*)d_in[5];
    const float* Wo      = (const float*)d_in[6];
    float* out = (float*)d_out;

    __nv_bfloat16 *iqh,*iql,*ikh,*ikl,*ivh,*ivl;
    __nv_bfloat16 *wqh,*wql,*wkh,*wkl,*wvh,*wvl,*woh,*wol;
    __nv_bfloat16 *Qh,*Ql,*Kh,*Kl,*Vh,*Vl,*Ch,*Cl;
    cudaGetSymbolAddress((void**)&iqh, g_iqh); cudaGetSymbolAddress((void**)&iql, g_iql);
    cudaGetSymbolAddress((void**)&ikh, g_ikh); cudaGetSymbolAddress((void**)&ikl, g_ikl);
    cudaGetSymbolAddress((void**)&ivh, g_ivh); cudaGetSymbolAddress((void**)&ivl, g_ivl);
    cudaGetSymbolAddress((void**)&wqh, g_wqh); cudaGetSymbolAddress((void**)&wql, g_wql);
    cudaGetSymbolAddress((void**)&wkh, g_wkh); cudaGetSymbolAddress((void**)&wkl, g_wkl);
    cudaGetSymbolAddress((void**)&wvh, g_wvh); cudaGetSymbolAddress((void**)&wvl, g_wvl);
    cudaGetSymbolAddress((void**)&woh, g_woh); cudaGetSymbolAddress((void**)&wol, g_wol);
    cudaGetSymbolAddress((void**)&Qh, g_Qh); cudaGetSymbolAddress((void**)&Ql, g_Ql);
    cudaGetSymbolAddress((void**)&Kh, g_Kh); cudaGetSymbolAddress((void**)&Kl, g_Kl);
    cudaGetSymbolAddress((void**)&Vh, g_Vh); cudaGetSymbolAddress((void**)&Vl, g_Vl);
    cudaGetSymbolAddress((void**)&Ch, g_Ch); cudaGetSymbolAddress((void**)&Cl, g_Cl);

    cudaFuncSetAttribute(gemm_qkv, cudaFuncAttributeMaxDynamicSharedMemorySize, GEMM_SMEM);
    cudaFuncSetAttribute(gemm_wo,  cudaFuncAttributeMaxDynamicSharedMemorySize, GEMM_SMEM);
    cudaFuncSetAttribute(attn_mma, cudaFuncAttributeMaxDynamicSharedMemorySize, ATTN_SMEM);

    // ---- splits ----
    split_k<<<NELEM / 4 / 256, 256>>>(queries, iqh, iql, NELEM / 4);
    split_k<<<NELEM / 4 / 256, 256>>>(keys,    ikh, ikl, NELEM / 4);
    split_k<<<NELEM / 4 / 256, 256>>>(values,  ivh, ivl, NELEM / 4);
    split_k<<<WELEM / 4 / 256, 256>>>(Wq, wqh, wql, WELEM / 4);
    split_k<<<WELEM / 4 / 256, 256>>>(Wk, wkh, wkl, WELEM / 4);
    split_k<<<WELEM / 4 / 256, 256>>>(Wv, wvh, wvl, WELEM / 4);
    split_k<<<WELEM / 4 / 256, 256>>>(Wo, woh, wol, WELEM / 4);

    // ---- fused QKV projection ----
    G3 g;
    g.Ah[0] = iqh; g.Al[0] = iql; g.Bh[0] = wqh; g.Bl[0] = wql; g.Ch[0] = Qh; g.Cl[0] = Ql; g.alpha[0] = 0.125f;
    g.Ah[1] = ikh; g.Al[1] = ikl; g.Bh[1] = wkh; g.Bl[1] = wkl; g.Ch[1] = Kh; g.Cl[1] = Kl; g.alpha[1] = 1.0f;
    g.Ah[2] = ivh; g.Al[2] = ivl; g.Bh[2] = wvh; g.Bl[2] = wvl; g.Ch[2] = Vh; g.Cl[2] = Vl; g.alpha[2] = 1.0f;

    gemm_qkv<<<dim3(DD / 128, MROWS / 128, 3), 256, GEMM_SMEM>>>(g);

    attn_mma<<<dim3(SS / 64, HH, BB), 256, ATTN_SMEM>>>(Qh, Ql, Kh, Kl, Vh, Vl, Ch, Cl);

    gemm_wo<<<dim3(DD / 128, MROWS / 128), 256, GEMM_SMEM>>>(Ch, Cl, woh, wol, out);
}

// round 13
// speedup vs baseline: 1.9946x; 1.9120x over previous
#include <cuda_runtime.h>
#include <cuda_fp16.h>
#include <mma.h>
#include <math.h>
#include <stdint.h>

using namespace nvcuda;

// Problem constants
#define BB 2
#define SS 2048
#define DD 1024
#define HH 16
#define HD 64
#define MROWS (BB*SS)      // 4096
#define NELEM (BB*SS*DD)   // 4M
#define WELEM (DD*DD)      // 1M

// ---------------------------------------------------------------------------
// Global scratch: A-side tensors as fp16 hi/lo, B-side tensors single fp16.
// ---------------------------------------------------------------------------
__device__ __half g_iqh[NELEM], g_iql[NELEM];   // split(queries)
__device__ __half g_ikh[NELEM], g_ikl[NELEM];   // split(keys)
__device__ __half g_ivh[NELEM], g_ivl[NELEM];   // split(values)
__device__ __half g_wq[WELEM], g_wk[WELEM], g_wv[WELEM], g_wo[WELEM];
__device__ __half g_Qh[NELEM], g_Ql[NELEM];     // projected Q hi/lo (A-side)
__device__ __half g_K[NELEM];                   // projected K single (B-side)
__device__ __half g_V[NELEM];                   // projected V single (B-side)
__device__ __half g_Ch[NELEM], g_Cl[NELEM];     // ctx hi/lo (A-side of Wo)

// Pack two floats -> f16x2 hi + f16x2 lo.
__device__ __forceinline__ void split2h(float x, float y, uint32_t& hi, uint32_t& lo) {
    __half2 h = __floats2half2_rn(x, y);
    float hx = __low2float(h), hy = __high2float(h);
    __half2 l = __floats2half2_rn(x - hx, y - hy);
    hi = *(uint32_t*)&h; lo = *(uint32_t*)&l;
}
__device__ __forceinline__ uint32_t pack2h(float x, float y) {
    __half2 h = __floats2half2_rn(x, y);
    return *(uint32_t*)&h;
}

__device__ __forceinline__ uint32_t smem_u32(const void* p) {
    uint32_t a;
    asm("{ .reg .u64 t; cvta.to.shared.u64 t, %1; cvt.u32.u64 %0, t; }"
        : "=r"(a) : "l"(p));
    return a;
}
__device__ __forceinline__ void cp16(uint32_t dst, const void* src) {
    asm volatile("cp.async.cg.shared.global [%0], [%1], 16;" :: "r"(dst), "l"(src));
}
__device__ __forceinline__ void ldsm_x4(uint32_t* r, uint32_t addr) {
    asm volatile("ldmatrix.sync.aligned.m8n8.x4.shared.b16 {%0,%1,%2,%3}, [%4];"
        : "=r"(r[0]), "=r"(r[1]), "=r"(r[2]), "=r"(r[3]) : "r"(addr));
}
__device__ __forceinline__ void ldsm_x4_t(uint32_t* r, uint32_t addr) {
    asm volatile("ldmatrix.sync.aligned.m8n8.x4.trans.shared.b16 {%0,%1,%2,%3}, [%4];"
        : "=r"(r[0]), "=r"(r[1]), "=r"(r[2]), "=r"(r[3]) : "r"(addr));
}
__device__ __forceinline__ void mma16816(float* c, const uint32_t* a, uint32_t b0, uint32_t b1) {
    asm volatile(
        "mma.sync.aligned.m16n8k16.row.col.f32.f16.f16.f32 "
        "{%0,%1,%2,%3}, {%4,%5,%6,%7}, {%8,%9}, {%0,%1,%2,%3};"
        : "+f"(c[0]), "+f"(c[1]), "+f"(c[2]), "+f"(c[3])
        : "r"(a[0]), "r"(a[1]), "r"(a[2]), "r"(a[3]), "r"(b0), "r"(b1));
}

// ===========================================================================
// Fused prep: 3 inputs split to fp16 hi/lo, 4 weights converted to fp16.
// Segments: [0,3): 4096 blocks each (1M float4); [3,7): 1024 blocks each.
// ===========================================================================
struct Prep {
    const float4* src[7];
    uint2* h[7];
    uint2* l[7];   // null for convert-only segs
};

__global__ __launch_bounds__(256) void prep_all(Prep p)
{
    int blk = blockIdx.x;
    int seg, ib;
    if (blk < 12288) { seg = blk >> 12; ib = blk & 4095; }
    else { int r = blk - 12288; seg = 3 + (r >> 10); ib = r & 1023; }
    int i = ib * 256 + threadIdx.x;

    float4 v = p.src[seg][i];
    __half2 h0 = __floats2half2_rn(v.x, v.y);
    __half2 h1 = __floats2half2_rn(v.z, v.w);
    uint2 hh;
    hh.x = *(uint32_t*)&h0; hh.y = *(uint32_t*)&h1;
    p.h[seg][i] = hh;
    if (seg < 3) {
        __half2 l0 = __floats2half2_rn(v.x - __low2float(h0), v.y - __high2float(h0));
        __half2 l1 = __floats2half2_rn(v.z - __low2float(h1), v.w - __high2float(h1));
        uint2 ll;
        ll.x = *(uint32_t*)&l0; ll.y = *(uint32_t*)&l1;
        p.l[seg][i] = ll;
    }
}

// ===========================================================================
// 2-term GEMM: C = alpha * (Ah + Al) @ B, A hi/lo fp16, B single fp16.
// 128x128 tile, BK=32, 2-stage cp.async, 8 warps (4x2), warp tile 32x64.
// ===========================================================================
#define BK 32
#define NC (DD / BK)       // 32
#define LDAs 40
#define LDBs 136
#define STG_A (128 * LDAs)           // 5120 halves
#define STG_B (BK * LDBs)            // 4352 halves
#define OFF_AL (STG_A * 2)           // 10240 B
#define OFF_B  (2 * STG_A * 2)       // 20480 B
#define STG_BYTES ((2 * STG_A + STG_B) * 2)   // 29184
#define GEMM_SMEM 65536              // 2 stages (58368) + epilogue staging room

__device__ __forceinline__ void issue_stage(
    uint32_t st, const __half* __restrict__ Ahg, const __half* __restrict__ Alg,
    const __half* __restrict__ Bg, int brow, int bcol, int k0, int tid)
{
    // A hi+lo: 1024 x 16B chunks, 4 per thread
    #pragma unroll
    for (int j = 0; j < 4; j++) {
        int c  = tid + 256 * j;
        const __half* Ag = (c < 512) ? Ahg : Alg;
        int c2 = c & 511;
        int r  = c2 >> 2;
        int q  = c2 & 3;
        uint32_t dst = st + ((c < 512) ? 0u : (uint32_t)OFF_AL)
                     + (uint32_t)r * (LDAs * 2) + (uint32_t)q * 16;
        cp16(dst, Ag + (size_t)(brow + r) * DD + k0 + q * 8);
    }
    // B: 512 x 16B chunks, 2 per thread
    #pragma unroll
    for (int j = 0; j < 2; j++) {
        int c  = tid + 256 * j;
        int kr = c >> 4;
        int cc = c & 15;
        uint32_t dst = st + OFF_B + (uint32_t)kr * (LDBs * 2) + (uint32_t)cc * 16;
        cp16(dst, Bg + (size_t)(k0 + kr) * DD + bcol + cc * 8);
    }
}

__device__ __forceinline__ void gemm_mainloop(
    char* smraw, uint32_t sb,
    const __half* __restrict__ Ahg, const __half* __restrict__ Alg,
    const __half* __restrict__ Bg,
    int brow, int bcol, int tid, int wm, int wn,
    wmma::fragment<wmma::accumulator, 16, 16, 16, float> (&acc)[2][4])
{
    #pragma unroll
    for (int i = 0; i < 2; i++)
        #pragma unroll
        for (int j = 0; j < 4; j++)
            wmma::fill_fragment(acc[i][j], 0.0f);

    issue_stage(sb, Ahg, Alg, Bg, brow, bcol, 0, tid);
    asm volatile("cp.async.commit_group;" ::: "memory");

    for (int c = 0; c < NC; c++) {
        const int st = c & 1;
        if (c + 1 < NC) {
            issue_stage(sb + (st ^ 1) * STG_BYTES, Ahg, Alg, Bg,
                        brow, bcol, (c + 1) * BK, tid);
            asm volatile("cp.async.commit_group;" ::: "memory");
            asm volatile("cp.async.wait_group 1;" ::: "memory");
        } else {
            asm volatile("cp.async.wait_group 0;" ::: "memory");
        }
        __syncthreads();

        const __half* Ah = (const __half*)(smraw + st * STG_BYTES);
        const __half* Al = Ah + STG_A;
        const __half* Bs = Al + STG_A;

        #pragma unroll
        for (int ks = 0; ks < 2; ks++) {
            wmma::fragment<wmma::matrix_a, 16, 16, 16, __half, wmma::row_major> ah[2], al[2];
            wmma::fragment<wmma::matrix_b, 16, 16, 16, __half, wmma::row_major> bf[4];
            #pragma unroll
            for (int i = 0; i < 2; i++) {
                wmma::load_matrix_sync(ah[i], Ah + (wm * 32 + i * 16) * LDAs + ks * 16, LDAs);
                wmma::load_matrix_sync(al[i], Al + (wm * 32 + i * 16) * LDAs + ks * 16, LDAs);
            }
            #pragma unroll
            for (int j = 0; j < 4; j++)
                wmma::load_matrix_sync(bf[j], Bs + (ks * 16) * LDBs + wn * 64 + j * 16, LDBs);
            #pragma unroll
            for (int i = 0; i < 2; i++)
                #pragma unroll
                for (int j = 0; j < 4; j++) {
                    wmma::mma_sync(acc[i][j], ah[i], bf[j], acc[i][j]);
                    wmma::mma_sync(acc[i][j], al[i], bf[j], acc[i][j]);
                }
        }
        __syncthreads();
    }
}

// ---- fused Q/K/V projection: z=0 -> Q hi/lo, z=1 -> K single, z=2 -> V single
struct G3 {
    const __half *Ah[3], *Al[3], *Bw[3];
    __half *C1[3], *C2[3];   // z=0: (Qh,Ql); z=1: (K,null); z=2: (V,null)
    float alpha[3];
};

__global__ __launch_bounds__(256) void gemm_qkv(G3 g)
{
    extern __shared__ char smraw[];
    const uint32_t sb = smem_u32(smraw);
    const int tid  = threadIdx.x;
    const int wid  = tid >> 5;
    const int lane = tid & 31;
    const int wm   = wid & 3;
    const int wn   = wid >> 2;
    const int brow = blockIdx.y * 128;
    const int bcol = blockIdx.x * 128;
    const int z    = blockIdx.z;

    wmma::fragment<wmma::accumulator, 16, 16, 16, float> acc[2][4];
    gemm_mainloop(smraw, sb, g.Ah[z], g.Al[z], g.Bw[z], brow, bcol, tid, wm, wn, acc);

    const float alpha = g.alpha[z];
    #pragma unroll
    for (int i = 0; i < 2; i++)
        #pragma unroll
        for (int j = 0; j < 4; j++)
            #pragma unroll
            for (int e = 0; e < acc[i][j].num_elements; e++)
                acc[i][j].x[e] *= alpha;

    // stage warp patch (32x64 fp32) in smem
    float* ws = (float*)(smraw) + wid * 2048;
    #pragma unroll
    for (int i = 0; i < 2; i++)
        #pragma unroll
        for (int j = 0; j < 4; j++)
            wmma::store_matrix_sync(ws + i * 16 * 64 + j * 16, acc[i][j], 64, wmma::mem_row_major);
    __syncwarp();
    const float* src = ws + lane * 64;
    int grow = brow + wm * 32 + lane;
    size_t obase = (size_t)grow * DD + bcol + wn * 64;

    if (z == 0) {
        __half* chp = g.C1[0] + obase;
        __half* clp = g.C2[0] + obase;
        #pragma unroll
        for (int gg = 0; gg < 8; gg++) {
            uint4 hv, lv;
            split2h(src[8 * gg + 0], src[8 * gg + 1], hv.x, lv.x);
            split2h(src[8 * gg + 2], src[8 * gg + 3], hv.y, lv.y);
            split2h(src[8 * gg + 4], src[8 * gg + 5], hv.z, lv.z);
            split2h(src[8 * gg + 6], src[8 * gg + 7], hv.w, lv.w);
            *(uint4*)(chp + 8 * gg) = hv;
            *(uint4*)(clp + 8 * gg) = lv;
        }
    } else {
        __half* cp = g.C1[z] + obase;
        #pragma unroll
        for (int gg = 0; gg < 8; gg++) {
            uint4 hv;
            hv.x = pack2h(src[8 * gg + 0], src[8 * gg + 1]);
            hv.y = pack2h(src[8 * gg + 2], src[8 * gg + 3]);
            hv.z = pack2h(src[8 * gg + 4], src[8 * gg + 5]);
            hv.w = pack2h(src[8 * gg + 6], src[8 * gg + 7]);
            *(uint4*)(cp + 8 * gg) = hv;
        }
    }
}

__global__ __launch_bounds__(256) void gemm_wo(
    const __half* __restrict__ Ahg, const __half* __restrict__ Alg,
    const __half* __restrict__ Bg, float* __restrict__ Cf)
{
    extern __shared__ char smraw[];
    const uint32_t sb = smem_u32(smraw);
    const int tid  = threadIdx.x;
    const int wid  = tid >> 5;
    const int wm   = wid & 3;
    const int wn   = wid >> 2;
    const int brow = blockIdx.y * 128;
    const int bcol = blockIdx.x * 128;

    wmma::fragment<wmma::accumulator, 16, 16, 16, float> acc[2][4];
    gemm_mainloop(smraw, sb, Ahg, Alg, Bg, brow, bcol, tid, wm, wn, acc);

    #pragma unroll
    for (int i = 0; i < 2; i++)
        #pragma unroll
        for (int j = 0; j < 4; j++) {
            float* Cp = Cf + (size_t)(brow + wm * 32 + i * 16) * DD + bcol + wn * 64 + j * 16;
            wmma::store_matrix_sync(Cp, acc[i][j], DD, wmma::mem_row_major);
        }
}

// ===========================================================================
// Raw-mma flash attention: Q hi/lo (A-side), K and V single fp16 (B-side).
// q-tile 64, kv-tile 64, double-buffered cp.async KV staging.
// ===========================================================================
#define LQ  72
#define LSO 72
#define KVB_BYTES (2 * 64 * LQ * 2)   // K + V single fp16 per buffer = 18432 B
#define ATTN_SMEM (2 * KVB_BYTES)     // 36864 (also exactly the epilogue obuf)

__global__ __launch_bounds__(256, 2) void attn_mma(
    const __half* __restrict__ Qhg, const __half* __restrict__ Qlg,
    const __half* __restrict__ Kg,  const __half* __restrict__ Vg,
    __half* __restrict__ Chg, __half* __restrict__ Clg)
{
    extern __shared__ char smraw[];
    __half* KVs = (__half*)smraw;
    __shared__ float lbuf[2][64];

    const int tid  = threadIdx.x;
    const int lane = tid & 31;
    const int wid  = tid >> 5;
    const int rm   = wid >> 1;
    const int cn   = wid & 1;
    const int q0   = blockIdx.x * 64;
    const int h    = blockIdx.y;
    const int b    = blockIdx.z;
    const int row  = tid >> 2;
    const int cseg = (tid & 3) * 16;
    const size_t hoff = (size_t)h * HD;
    const size_t gbase = ((size_t)(b * SS) + q0 + row) * DD + hoff + cseg;

    const uint32_t base = smem_u32(KVs);
    const int rA = lane & 15, cA = (lane >> 4) * 8;
    const int rK = (lane & 7) + ((lane & 16) >> 1), cK = lane & 8;

    // ---- stage Q hi/lo in buffer-1 region, hoist A-fragments ------------
    {
        int bi = row * LQ + cseg;
        *(uint4*)&KVs[KVB_BYTES / 2 + bi]               = *(const uint4*)(Qhg + gbase);
        *(uint4*)&KVs[KVB_BYTES / 2 + bi + 8]           = *(const uint4*)(Qhg + gbase + 8);
        *(uint4*)&KVs[KVB_BYTES / 2 + 64 * LQ + bi]     = *(const uint4*)(Qlg + gbase);
        *(uint4*)&KVs[KVB_BYTES / 2 + 64 * LQ + bi + 8] = *(const uint4*)(Qlg + gbase + 8);
    }
    __syncthreads();

    // KV tile issue for buffer `buf` (K at +0, V at +64*LQ*2), 4 cp16/thread
    auto issue_kv = [&](int buf, int kv0) {
        const size_t kb = ((size_t)(b * SS) + kv0 + row) * DD + hoff + cseg;
        uint32_t bb = base + (uint32_t)buf * KVB_BYTES + (uint32_t)(row * LQ + cseg) * 2;
        cp16(bb,      Kg + kb);
        cp16(bb + 16, Kg + kb + 8);
        cp16(bb + 64 * LQ * 2,      Vg + kb);
        cp16(bb + 64 * LQ * 2 + 16, Vg + kb + 8);
    };

    issue_kv(0, 0);   // buf0; does not touch Q staging area (buf1)
    asm volatile("cp.async.commit_group;" ::: "memory");

    uint32_t qh[4][4], ql[4][4];
    #pragma unroll
    for (int d = 0; d < 4; d++) {
        uint32_t a = base + (uint32_t)KVB_BYTES
                   + (uint32_t)((rm * 16 + rA) * LQ + d * 16 + cA) * 2;
        ldsm_x4(qh[d], a);
        ldsm_x4(ql[d], a + 64 * LQ * 2);
    }
    __syncthreads();   // all Q-frag loads done before loop overwrites buf1

    float oacc[8][4];
    #pragma unroll
    for (int n = 0; n < 8; n++)
        #pragma unroll
        for (int e = 0; e < 4; e++) oacc[n][e] = 0.0f;
    float ls0 = 0.0f, ls1 = 0.0f;

    for (int c = 0; c < SS / 64; c++) {
        if (c + 1 < SS / 64) {
            issue_kv((c + 1) & 1, (c + 1) * 64);
            asm volatile("cp.async.commit_group;" ::: "memory");
            asm volatile("cp.async.wait_group 1;" ::: "memory");
        } else {
            asm volatile("cp.async.wait_group 0;" ::: "memory");
        }
        __syncthreads();

        const uint32_t bb = base + (uint32_t)(c & 1) * KVB_BYTES;

        // ---- S = Q @ K^T (2-term: qh@k + ql@k) --------------------------
        float s[4][4];
        #pragma unroll
        for (int j = 0; j < 4; j++)
            #pragma unroll
            for (int e = 0; e < 4; e++) s[j][e] = 0.0f;

        #pragma unroll
        for (int d = 0; d < 4; d++) {
            #pragma unroll
            for (int jp = 0; jp < 2; jp++) {
                uint32_t kf[4];
                uint32_t a = bb + (uint32_t)((cn * 32 + jp * 16 + rK) * LQ + d * 16 + cK) * 2;
                ldsm_x4(kf, a);
                mma16816(s[jp * 2],     qh[d], kf[0], kf[1]);
                mma16816(s[jp * 2],     ql[d], kf[0], kf[1]);
                mma16816(s[jp * 2 + 1], qh[d], kf[2], kf[3]);
                mma16816(s[jp * 2 + 1], ql[d], kf[2], kf[3]);
            }
        }

        // ---- exp + row-sum ----------------------------------------------
        #pragma unroll
        for (int j = 0; j < 4; j++) {
            s[j][0] = __expf(s[j][0]); s[j][1] = __expf(s[j][1]);
            s[j][2] = __expf(s[j][2]); s[j][3] = __expf(s[j][3]);
            ls0 += s[j][0] + s[j][1];
            ls1 += s[j][2] + s[j][3];
        }

        // ---- repack P -> fp16 hi/lo A fragments (register-only) ----------
        uint32_t ph[2][4], pl[2][4];
        #pragma unroll
        for (int kk = 0; kk < 2; kk++) {
            int j0 = kk * 2;
            split2h(s[j0][0],     s[j0][1],     ph[kk][0], pl[kk][0]);
            split2h(s[j0][2],     s[j0][3],     ph[kk][1], pl[kk][1]);
            split2h(s[j0 + 1][0], s[j0 + 1][1], ph[kk][2], pl[kk][2]);
            split2h(s[j0 + 1][2], s[j0 + 1][3], ph[kk][3], pl[kk][3]);
        }

        // ---- O_partial += P @ V (2-term: ph@v + pl@v) --------------------
        #pragma unroll
        for (int kk = 0; kk < 2; kk++) {
            #pragma unroll
            for (int np = 0; np < 4; np++) {
                uint32_t vf[4];
                uint32_t a = bb + (uint32_t)(64 * LQ * 2)
                           + (uint32_t)((cn * 32 + kk * 16 + rA) * LQ + np * 16 + cA) * 2;
                ldsm_x4_t(vf, a);
                mma16816(oacc[np * 2],     ph[kk], vf[0], vf[1]);
                mma16816(oacc[np * 2],     pl[kk], vf[0], vf[1]);
                mma16816(oacc[np * 2 + 1], ph[kk], vf[2], vf[3]);
                mma16816(oacc[np * 2 + 1], pl[kk], vf[2], vf[3]);
            }
        }
        __syncthreads();   // reads of buf (c&1) done before iter c+1 rewrites it
    }

    // ---- row-sum halves ----------------------------------------------------
    ls0 += __shfl_xor_sync(0xffffffffu, ls0, 1);
    ls0 += __shfl_xor_sync(0xffffffffu, ls0, 2);
    ls1 += __shfl_xor_sync(0xffffffffu, ls1, 1);
    ls1 += __shfl_xor_sync(0xffffffffu, ls1, 2);
    if ((lane & 3) == 0) {
        lbuf[cn][rm * 16 + (lane >> 2)]     = ls0;
        lbuf[cn][rm * 16 + (lane >> 2) + 8] = ls1;
    }
    __syncthreads();

    // ---- merge O partials through smem (aliased over both KV buffers) ------
    float* obuf = (float*)smraw;   // [2][64][LSO] fp32 = 36864 B, exact fit
    {
        int r0 = rm * 16 + (lane >> 2);
        int c0 = (lane & 3) * 2;
        float* ob = obuf + cn * 64 * LSO;
        #pragma unroll
        for (int n = 0; n < 8; n++) {
            float2 lo; lo.x = oacc[n][0]; lo.y = oacc[n][1];
            float2 hi; hi.x = oacc[n][2]; hi.y = oacc[n][3];
            *(float2*)&ob[r0 * LSO + n * 8 + c0]       = lo;
            *(float2*)&ob[(r0 + 8) * LSO + n * 8 + c0] = hi;
        }
    }
    __syncthreads();

    // ---- normalize + split-write ctx fp16 hi/lo -----------------------------
    {
        const float inv = 1.0f / (lbuf[0][row] + lbuf[1][row]);
        __half* chp = Chg + gbase;
        __half* clp = Clg + gbase;
        #pragma unroll
        for (int g = 0; g < 2; g++) {
            float v[8];
            #pragma unroll
            for (int e = 0; e < 8; e++) {
                int cc = cseg + g * 8 + e;
                v[e] = (obuf[row * LSO + cc] + obuf[64 * LSO + row * LSO + cc]) * inv;
            }
            uint4 hv, lv;
            split2h(v[0], v[1], hv.x, lv.x);
            split2h(v[2], v[3], hv.y, lv.y);
            split2h(v[4], v[5], hv.z, lv.z);
            split2h(v[6], v[7], hv.w, lv.w);
            *(uint4*)(chp + g * 8) = hv;
            *(uint4*)(clp + g * 8) = lv;
        }
    }
}

// ---------------------------------------------------------------------------
extern "C" void kernel_launch(void* const* d_in, const int* in_sizes, int n_in,
                              void* d_out, int out_size)
{
    const float* queries = (const float*)d_in[0];
    const float* keys    = (const float*)d_in[1];
    const float* values  = (const float*)d_in[2];
    const float* Wq      = (const float*)d_in[3];
    const float* Wk      = (const float*)d_in[4];
    const float* Wv      = (const float*)d_in[5];
    const float* Wo      = (const float*)d_in[6];
    float* out = (float*)d_out;

    __half *iqh,*iql,*ikh,*ikl,*ivh,*ivl;
    __half *wq,*wk,*wv,*wo;
    __half *Qh,*Ql,*Kb,*Vb,*Ch,*Cl;
    cudaGetSymbolAddress((void**)&iqh, g_iqh); cudaGetSymbolAddress((void**)&iql, g_iql);
    cudaGetSymbolAddress((void**)&ikh, g_ikh); cudaGetSymbolAddress((void**)&ikl, g_ikl);
    cudaGetSymbolAddress((void**)&ivh, g_ivh); cudaGetSymbolAddress((void**)&ivl, g_ivl);
    cudaGetSymbolAddress((void**)&wq, g_wq); cudaGetSymbolAddress((void**)&wk, g_wk);
    cudaGetSymbolAddress((void**)&wv, g_wv); cudaGetSymbolAddress((void**)&wo, g_wo);
    cudaGetSymbolAddress((void**)&Qh, g_Qh); cudaGetSymbolAddress((void**)&Ql, g_Ql);
    cudaGetSymbolAddress((void**)&Kb, g_K);  cudaGetSymbolAddress((void**)&Vb, g_V);
    cudaGetSymbolAddress((void**)&Ch, g_Ch); cudaGetSymbolAddress((void**)&Cl, g_Cl);

    cudaFuncSetAttribute(gemm_qkv, cudaFuncAttributeMaxDynamicSharedMemorySize, GEMM_SMEM);
    cudaFuncSetAttribute(gemm_wo,  cudaFuncAttributeMaxDynamicSharedMemorySize, GEMM_SMEM);
    cudaFuncSetAttribute(attn_mma, cudaFuncAttributeMaxDynamicSharedMemorySize, ATTN_SMEM);

    // ---- fused prep (3 splits + 4 converts) ----
    Prep p;
    p.src[0] = (const float4*)queries; p.h[0] = (uint2*)iqh; p.l[0] = (uint2*)iql;
    p.src[1] = (const float4*)keys;    p.h[1] = (uint2*)ikh; p.l[1] = (uint2*)ikl;
    p.src[2] = (const float4*)values;  p.h[2] = (uint2*)ivh; p.l[2] = (uint2*)ivl;
    p.src[3] = (const float4*)Wq; p.h[3] = (uint2*)wq; p.l[3] = nullptr;
    p.src[4] = (const float4*)Wk; p.h[4] = (uint2*)wk; p.l[4] = nullptr;
    p.src[5] = (const float4*)Wv; p.h[5] = (uint2*)wv; p.l[5] = nullptr;
    p.src[6] = (const float4*)Wo; p.h[6] = (uint2*)wo; p.l[6] = nullptr;
    prep_all<<<16384, 256>>>(p);

    // ---- fused QKV projection ----
    G3 g;
    g.Ah[0] = iqh; g.Al[0] = iql; g.Bw[0] = wq; g.C1[0] = Qh; g.C2[0] = Ql; g.alpha[0] = 0.125f;
    g.Ah[1] = ikh; g.Al[1] = ikl; g.Bw[1] = wk; g.C1[1] = Kb; g.C2[1] = nullptr; g.alpha[1] = 1.0f;
    g.Ah[2] = ivh; g.Al[2] = ivl; g.Bw[2] = wv; g.C1[2] = Vb; g.C2[2] = nullptr; g.alpha[2] = 1.0f;

    gemm_qkv<<<dim3(DD / 128, MROWS / 128, 3), 256, GEMM_SMEM>>>(g);

    attn_mma<<<dim3(SS / 64, HH, BB), 256, ATTN_SMEM>>>(Qh, Ql, Kb, Vb, Ch, Cl);

    gemm_wo<<<dim3(DD / 128, MROWS / 128), 256, GEMM_SMEM>>>(Ch, Cl, wo, out);
}

// round 14
// speedup vs baseline: 2.2041x; 1.1051x over previous
#include <cuda_runtime.h>
#include <cuda_fp16.h>
#include <mma.h>
#include <math.h>
#include <stdint.h>

using namespace nvcuda;

// Problem constants
#define BB 2
#define SS 2048
#define DD 1024
#define HH 16
#define HD 64
#define MROWS (BB*SS)      // 4096
#define NELEM (BB*SS*DD)   // 4M
#define WELEM (DD*DD)      // 1M

// ---------------------------------------------------------------------------
// Global scratch: A-side tensors as fp16 hi/lo, B-side tensors single fp16.
// ---------------------------------------------------------------------------
__device__ __half g_iqh[NELEM], g_iql[NELEM];
__device__ __half g_ikh[NELEM], g_ikl[NELEM];
__device__ __half g_ivh[NELEM], g_ivl[NELEM];
__device__ __half g_wq[WELEM], g_wk[WELEM], g_wv[WELEM], g_wo[WELEM];
__device__ __half g_Qh[NELEM], g_Ql[NELEM];
__device__ __half g_K[NELEM];
__device__ __half g_V[NELEM];
__device__ __half g_Ch[NELEM], g_Cl[NELEM];

__device__ __forceinline__ void split2h(float x, float y, uint32_t& hi, uint32_t& lo) {
    __half2 h = __floats2half2_rn(x, y);
    float hx = __low2float(h), hy = __high2float(h);
    __half2 l = __floats2half2_rn(x - hx, y - hy);
    hi = *(uint32_t*)&h; lo = *(uint32_t*)&l;
}
__device__ __forceinline__ uint32_t pack2h(float x, float y) {
    __half2 h = __floats2half2_rn(x, y);
    return *(uint32_t*)&h;
}

__device__ __forceinline__ uint32_t smem_u32(const void* p) {
    uint32_t a;
    asm("{ .reg .u64 t; cvta.to.shared.u64 t, %1; cvt.u32.u64 %0, t; }"
        : "=r"(a) : "l"(p));
    return a;
}
__device__ __forceinline__ void cp16(uint32_t dst, const void* src) {
    asm volatile("cp.async.cg.shared.global [%0], [%1], 16;" :: "r"(dst), "l"(src));
}
__device__ __forceinline__ void ldsm_x4(uint32_t* r, uint32_t addr) {
    asm volatile("ldmatrix.sync.aligned.m8n8.x4.shared.b16 {%0,%1,%2,%3}, [%4];"
        : "=r"(r[0]), "=r"(r[1]), "=r"(r[2]), "=r"(r[3]) : "r"(addr));
}
__device__ __forceinline__ void ldsm_x4_t(uint32_t* r, uint32_t addr) {
    asm volatile("ldmatrix.sync.aligned.m8n8.x4.trans.shared.b16 {%0,%1,%2,%3}, [%4];"
        : "=r"(r[0]), "=r"(r[1]), "=r"(r[2]), "=r"(r[3]) : "r"(addr));
}
__device__ __forceinline__ void mma16816(float* c, const uint32_t* a, uint32_t b0, uint32_t b1) {
    asm volatile(
        "mma.sync.aligned.m16n8k16.row.col.f32.f16.f16.f32 "
        "{%0,%1,%2,%3}, {%4,%5,%6,%7}, {%8,%9}, {%0,%1,%2,%3};"
        : "+f"(c[0]), "+f"(c[1]), "+f"(c[2]), "+f"(c[3])
        : "r"(a[0]), "r"(a[1]), "r"(a[2]), "r"(a[3]), "r"(b0), "r"(b1));
}

// ===========================================================================
// Fused prep with MLP=4: each thread handles 4 independent float4.
// Segments: [0,3): inputs (split hi/lo), 1024 blocks each;
//           [3,7): weights (convert),     256 blocks each.  Total 4096 blocks.
// ===========================================================================
struct Prep {
    const float4* src[7];
    uint2* h[7];
    uint2* l[7];
};

__global__ __launch_bounds__(256) void prep_all(Prep p)
{
    int blk = blockIdx.x;
    int seg, ib;
    if (blk < 3072) { seg = blk >> 10; ib = blk & 1023; }
    else { int r = blk - 3072; seg = 3 + (r >> 8); ib = r & 255; }
    const float4* src = p.src[seg];
    uint2* hp = p.h[seg];
    uint2* lp = p.l[seg];
    int i0 = ib * 1024 + threadIdx.x;

    float4 v[4];
    #pragma unroll
    for (int j = 0; j < 4; j++) v[j] = src[i0 + j * 256];   // 4 loads in flight

    if (seg < 3) {
        #pragma unroll
        for (int j = 0; j < 4; j++) {
            __half2 h0 = __floats2half2_rn(v[j].x, v[j].y);
            __half2 h1 = __floats2half2_rn(v[j].z, v[j].w);
            uint2 hh; hh.x = *(uint32_t*)&h0; hh.y = *(uint32_t*)&h1;
            hp[i0 + j * 256] = hh;
            __half2 l0 = __floats2half2_rn(v[j].x - __low2float(h0), v[j].y - __high2float(h0));
            __half2 l1 = __floats2half2_rn(v[j].z - __low2float(h1), v[j].w - __high2float(h1));
            uint2 ll; ll.x = *(uint32_t*)&l0; ll.y = *(uint32_t*)&l1;
            lp[i0 + j * 256] = ll;
        }
    } else {
        #pragma unroll
        for (int j = 0; j < 4; j++) {
            __half2 h0 = __floats2half2_rn(v[j].x, v[j].y);
            __half2 h1 = __floats2half2_rn(v[j].z, v[j].w);
            uint2 hh; hh.x = *(uint32_t*)&h0; hh.y = *(uint32_t*)&h1;
            hp[i0 + j * 256] = hh;
        }
    }
}

// ===========================================================================
// 2-term GEMM: C = alpha * (Ah + Al) @ B. 3-stage ring, ONE sync per chunk.
// 128x128 tile, BK=32, 8 warps (4x2), warp tile 32x64.
// ===========================================================================
#define BK 32
#define NC (DD / BK)       // 32
#define LDAs 40
#define LDBs 136
#define STG_A (128 * LDAs)           // 5120 halves
#define STG_B (BK * LDBs)            // 4352 halves
#define OFF_AL (STG_A * 2)
#define OFF_B  (2 * STG_A * 2)
#define STG_BYTES ((2 * STG_A + STG_B) * 2)   // 29184
#define GEMM_SMEM (3 * STG_BYTES)             // 87552 (>= 64KB epilogue staging)

__device__ __forceinline__ void issue_stage(
    uint32_t st, const __half* __restrict__ Ahg, const __half* __restrict__ Alg,
    const __half* __restrict__ Bg, int brow, int bcol, int k0, int tid)
{
    #pragma unroll
    for (int j = 0; j < 4; j++) {
        int c  = tid + 256 * j;
        const __half* Ag = (c < 512) ? Ahg : Alg;
        int c2 = c & 511;
        int r  = c2 >> 2;
        int q  = c2 & 3;
        uint32_t dst = st + ((c < 512) ? 0u : (uint32_t)OFF_AL)
                     + (uint32_t)r * (LDAs * 2) + (uint32_t)q * 16;
        cp16(dst, Ag + (size_t)(brow + r) * DD + k0 + q * 8);
    }
    #pragma unroll
    for (int j = 0; j < 2; j++) {
        int c  = tid + 256 * j;
        int kr = c >> 4;
        int cc = c & 15;
        uint32_t dst = st + OFF_B + (uint32_t)kr * (LDBs * 2) + (uint32_t)cc * 16;
        cp16(dst, Bg + (size_t)(k0 + kr) * DD + bcol + cc * 8);
    }
}

__device__ __forceinline__ void gemm_mainloop(
    char* smraw, uint32_t sb,
    const __half* __restrict__ Ahg, const __half* __restrict__ Alg,
    const __half* __restrict__ Bg,
    int brow, int bcol, int tid, int wm, int wn,
    wmma::fragment<wmma::accumulator, 16, 16, 16, float> (&acc)[2][4])
{
    #pragma unroll
    for (int i = 0; i < 2; i++)
        #pragma unroll
        for (int j = 0; j < 4; j++)
            wmma::fill_fragment(acc[i][j], 0.0f);

    issue_stage(sb, Ahg, Alg, Bg, brow, bcol, 0, tid);
    asm volatile("cp.async.commit_group;" ::: "memory");

    for (int c = 0; c < NC; c++) {
        const int st = c % 3;
        // S=3, d=1, one barrier/iter: issue(c+1) targets buf (c+1)%3 whose
        // readers were at iter c-2, protected by barrier(c-1).
        if (c + 1 < NC) {
            issue_stage(sb + (uint32_t)((c + 1) % 3) * STG_BYTES, Ahg, Alg, Bg,
                        brow, bcol, (c + 1) * BK, tid);
            asm volatile("cp.async.commit_group;" ::: "memory");
            asm volatile("cp.async.wait_group 1;" ::: "memory");
        } else {
            asm volatile("cp.async.wait_group 0;" ::: "memory");
        }
        __syncthreads();

        const __half* Ah = (const __half*)(smraw + st * STG_BYTES);
        const __half* Al = Ah + STG_A;
        const __half* Bs = Al + STG_A;

        #pragma unroll
        for (int ks = 0; ks < 2; ks++) {
            wmma::fragment<wmma::matrix_a, 16, 16, 16, __half, wmma::row_major> ah[2], al[2];
            wmma::fragment<wmma::matrix_b, 16, 16, 16, __half, wmma::row_major> bf[4];
            #pragma unroll
            for (int i = 0; i < 2; i++) {
                wmma::load_matrix_sync(ah[i], Ah + (wm * 32 + i * 16) * LDAs + ks * 16, LDAs);
                wmma::load_matrix_sync(al[i], Al + (wm * 32 + i * 16) * LDAs + ks * 16, LDAs);
            }
            #pragma unroll
            for (int j = 0; j < 4; j++)
                wmma::load_matrix_sync(bf[j], Bs + (ks * 16) * LDBs + wn * 64 + j * 16, LDBs);
            #pragma unroll
            for (int i = 0; i < 2; i++)
                #pragma unroll
                for (int j = 0; j < 4; j++) {
                    wmma::mma_sync(acc[i][j], ah[i], bf[j], acc[i][j]);
                    wmma::mma_sync(acc[i][j], al[i], bf[j], acc[i][j]);
                }
        }
        // no trailing sync (proof above)
    }
    __syncthreads();   // all smem reads done before epilogue aliases stages
}

// ---- fused Q/K/V projection: z=0 -> Q hi/lo, z=1 -> K single, z=2 -> V single
struct G3 {
    const __half *Ah[3], *Al[3], *Bw[3];
    __half *C1[3], *C2[3];
    float alpha[3];
};

__global__ __launch_bounds__(256, 2) void gemm_qkv(G3 g)
{
    extern __shared__ char smraw[];
    const uint32_t sb = smem_u32(smraw);
    const int tid  = threadIdx.x;
    const int wid  = tid >> 5;
    const int lane = tid & 31;
    const int wm   = wid & 3;
    const int wn   = wid >> 2;
    const int brow = blockIdx.y * 128;
    const int bcol = blockIdx.x * 128;
    const int z    = blockIdx.z;

    wmma::fragment<wmma::accumulator, 16, 16, 16, float> acc[2][4];
    gemm_mainloop(smraw, sb, g.Ah[z], g.Al[z], g.Bw[z], brow, bcol, tid, wm, wn, acc);

    const float alpha = g.alpha[z];
    #pragma unroll
    for (int i = 0; i < 2; i++)
        #pragma unroll
        for (int j = 0; j < 4; j++)
            #pragma unroll
            for (int e = 0; e < acc[i][j].num_elements; e++)
                acc[i][j].x[e] *= alpha;

    float* ws = (float*)(smraw) + wid * 2048;
    #pragma unroll
    for (int i = 0; i < 2; i++)
        #pragma unroll
        for (int j = 0; j < 4; j++)
            wmma::store_matrix_sync(ws + i * 16 * 64 + j * 16, acc[i][j], 64, wmma::mem_row_major);
    __syncwarp();
    const float* src = ws + lane * 64;
    int grow = brow + wm * 32 + lane;
    size_t obase = (size_t)grow * DD + bcol + wn * 64;

    if (z == 0) {
        __half* chp = g.C1[0] + obase;
        __half* clp = g.C2[0] + obase;
        #pragma unroll
        for (int gg = 0; gg < 8; gg++) {
            uint4 hv, lv;
            split2h(src[8 * gg + 0], src[8 * gg + 1], hv.x, lv.x);
            split2h(src[8 * gg + 2], src[8 * gg + 3], hv.y, lv.y);
            split2h(src[8 * gg + 4], src[8 * gg + 5], hv.z, lv.z);
            split2h(src[8 * gg + 6], src[8 * gg + 7], hv.w, lv.w);
            *(uint4*)(chp + 8 * gg) = hv;
            *(uint4*)(clp + 8 * gg) = lv;
        }
    } else {
        __half* cp = g.C1[z] + obase;
        #pragma unroll
        for (int gg = 0; gg < 8; gg++) {
            uint4 hv;
            hv.x = pack2h(src[8 * gg + 0], src[8 * gg + 1]);
            hv.y = pack2h(src[8 * gg + 2], src[8 * gg + 3]);
            hv.z = pack2h(src[8 * gg + 4], src[8 * gg + 5]);
            hv.w = pack2h(src[8 * gg + 6], src[8 * gg + 7]);
            *(uint4*)(cp + 8 * gg) = hv;
        }
    }
}

__global__ __launch_bounds__(256, 2) void gemm_wo(
    const __half* __restrict__ Ahg, const __half* __restrict__ Alg,
    const __half* __restrict__ Bg, float* __restrict__ Cf)
{
    extern __shared__ char smraw[];
    const uint32_t sb = smem_u32(smraw);
    const int tid  = threadIdx.x;
    const int wid  = tid >> 5;
    const int wm   = wid & 3;
    const int wn   = wid >> 2;
    const int brow = blockIdx.y * 128;
    const int bcol = blockIdx.x * 128;

    wmma::fragment<wmma::accumulator, 16, 16, 16, float> acc[2][4];
    gemm_mainloop(smraw, sb, Ahg, Alg, Bg, brow, bcol, tid, wm, wn, acc);

    #pragma unroll
    for (int i = 0; i < 2; i++)
        #pragma unroll
        for (int j = 0; j < 4; j++) {
            float* Cp = Cf + (size_t)(brow + wm * 32 + i * 16) * DD + bcol + wn * 64 + j * 16;
            wmma::store_matrix_sync(Cp, acc[i][j], DD, wmma::mem_row_major);
        }
}

// ===========================================================================
// Raw-mma flash attention: Q hi/lo (A-side), K/V single fp16 (B-side).
// 4-stage KV ring, prefetch distance 2, ONE sync per iteration.
// ===========================================================================
#define LQ  72
#define LSO 72
#define KVB_BYTES (2 * 64 * LQ * 2)   // K + V per buffer = 18432 B
#define ATTN_SMEM (4 * KVB_BYTES)     // 73728 (>= 36864 epilogue obuf)

__global__ __launch_bounds__(256, 2) void attn_mma(
    const __half* __restrict__ Qhg, const __half* __restrict__ Qlg,
    const __half* __restrict__ Kg,  const __half* __restrict__ Vg,
    __half* __restrict__ Chg, __half* __restrict__ Clg)
{
    extern __shared__ char smraw[];
    __half* KVs = (__half*)smraw;
    __shared__ float lbuf[2][64];

    const int tid  = threadIdx.x;
    const int lane = tid & 31;
    const int wid  = tid >> 5;
    const int rm   = wid >> 1;
    const int cn   = wid & 1;
    const int q0   = blockIdx.x * 64;
    const int h    = blockIdx.y;
    const int b    = blockIdx.z;
    const int row  = tid >> 2;
    const int cseg = (tid & 3) * 16;
    const size_t hoff = (size_t)h * HD;
    const size_t gbase = ((size_t)(b * SS) + q0 + row) * DD + hoff + cseg;

    const uint32_t base = smem_u32(KVs);
    const int rA = lane & 15, cA = (lane >> 4) * 8;
    const int rK = (lane & 7) + ((lane & 16) >> 1), cK = lane & 8;

    // KV tile issue for buffer `buf` (K at +0, V at +64*LQ*2), 4 cp16/thread
    auto issue_kv = [&](int buf, int kv0) {
        const size_t kb = ((size_t)(b * SS) + kv0 + row) * DD + hoff + cseg;
        uint32_t bb = base + (uint32_t)buf * KVB_BYTES + (uint32_t)(row * LQ + cseg) * 2;
        cp16(bb,      Kg + kb);
        cp16(bb + 16, Kg + kb + 8);
        cp16(bb + 64 * LQ * 2,      Vg + kb);
        cp16(bb + 64 * LQ * 2 + 16, Vg + kb + 8);
    };

    // ---- prologue: stage Q in buf3, prefetch chunks 0,1 ------------------
    {
        int bi = row * LQ + cseg;
        __half* q3 = KVs + 3 * (KVB_BYTES / 2);
        *(uint4*)&q3[bi]               = *(const uint4*)(Qhg + gbase);
        *(uint4*)&q3[bi + 8]           = *(const uint4*)(Qhg + gbase + 8);
        *(uint4*)&q3[64 * LQ + bi]     = *(const uint4*)(Qlg + gbase);
        *(uint4*)&q3[64 * LQ + bi + 8] = *(const uint4*)(Qlg + gbase + 8);
    }
    issue_kv(0, 0);
    asm volatile("cp.async.commit_group;" ::: "memory");
    issue_kv(1, 64);
    asm volatile("cp.async.commit_group;" ::: "memory");
    __syncthreads();   // Q generic stores visible

    uint32_t qh[4][4], ql[4][4];
    #pragma unroll
    for (int d = 0; d < 4; d++) {
        uint32_t a = base + 3u * KVB_BYTES
                   + (uint32_t)((rm * 16 + rA) * LQ + d * 16 + cA) * 2;
        ldsm_x4(qh[d], a);
        ldsm_x4(ql[d], a + 64 * LQ * 2);
    }
    __syncthreads();   // Q frag reads done before buf3 is reused (iter 1 issue)

    float oacc[8][4];
    #pragma unroll
    for (int n = 0; n < 8; n++)
        #pragma unroll
        for (int e = 0; e < 4; e++) oacc[n][e] = 0.0f;
    float ls0 = 0.0f, ls1 = 0.0f;

    for (int c = 0; c < SS / 64; c++) {
        // S=4, d=2, one barrier/iter: issue(c+2) targets buf (c+2)%4 whose
        // readers were at iter c-2, protected by barrier(c-1).
        if (c + 2 < SS / 64) {
            issue_kv((c + 2) & 3, (c + 2) * 64);
            asm volatile("cp.async.commit_group;" ::: "memory");
            asm volatile("cp.async.wait_group 2;" ::: "memory");
        } else if (c + 1 < SS / 64) {
            asm volatile("cp.async.wait_group 1;" ::: "memory");
        } else {
            asm volatile("cp.async.wait_group 0;" ::: "memory");
        }
        __syncthreads();

        const uint32_t bb = base + (uint32_t)(c & 3) * KVB_BYTES;

        // ---- S = Q @ K^T (2-term) --------------------------------------
        float s[4][4];
        #pragma unroll
        for (int j = 0; j < 4; j++)
            #pragma unroll
            for (int e = 0; e < 4; e++) s[j][e] = 0.0f;

        #pragma unroll
        for (int d = 0; d < 4; d++) {
            #pragma unroll
            for (int jp = 0; jp < 2; jp++) {
                uint32_t kf[4];
                uint32_t a = bb + (uint32_t)((cn * 32 + jp * 16 + rK) * LQ + d * 16 + cK) * 2;
                ldsm_x4(kf, a);
                mma16816(s[jp * 2],     qh[d], kf[0], kf[1]);
                mma16816(s[jp * 2],     ql[d], kf[0], kf[1]);
                mma16816(s[jp * 2 + 1], qh[d], kf[2], kf[3]);
                mma16816(s[jp * 2 + 1], ql[d], kf[2], kf[3]);
            }
        }

        // ---- exp + row-sum ----------------------------------------------
        #pragma unroll
        for (int j = 0; j < 4; j++) {
            s[j][0] = __expf(s[j][0]); s[j][1] = __expf(s[j][1]);
            s[j][2] = __expf(s[j][2]); s[j][3] = __expf(s[j][3]);
            ls0 += s[j][0] + s[j][1];
            ls1 += s[j][2] + s[j][3];
        }

        // ---- repack P -> fp16 hi/lo A fragments (register-only) ----------
        uint32_t ph[2][4], pl[2][4];
        #pragma unroll
        for (int kk = 0; kk < 2; kk++) {
            int j0 = kk * 2;
            split2h(s[j0][0],     s[j0][1],     ph[kk][0], pl[kk][0]);
            split2h(s[j0][2],     s[j0][3],     ph[kk][1], pl[kk][1]);
            split2h(s[j0 + 1][0], s[j0 + 1][1], ph[kk][2], pl[kk][2]);
            split2h(s[j0 + 1][2], s[j0 + 1][3], ph[kk][3], pl[kk][3]);
        }

        // ---- O_partial += P @ V (2-term) ----------------------------------
        #pragma unroll
        for (int kk = 0; kk < 2; kk++) {
            #pragma unroll
            for (int np = 0; np < 4; np++) {
                uint32_t vf[4];
                uint32_t a = bb + (uint32_t)(64 * LQ * 2)
                           + (uint32_t)((cn * 32 + kk * 16 + rA) * LQ + np * 16 + cA) * 2;
                ldsm_x4_t(vf, a);
                mma16816(oacc[np * 2],     ph[kk], vf[0], vf[1]);
                mma16816(oacc[np * 2],     pl[kk], vf[0], vf[1]);
                mma16816(oacc[np * 2 + 1], ph[kk], vf[2], vf[3]);
                mma16816(oacc[np * 2 + 1], pl[kk], vf[2], vf[3]);
            }
        }
        // no trailing sync (proof above)
    }

    // ---- row-sum halves ----------------------------------------------------
    ls0 += __shfl_xor_sync(0xffffffffu, ls0, 1);
    ls0 += __shfl_xor_sync(0xffffffffu, ls0, 2);
    ls1 += __shfl_xor_sync(0xffffffffu, ls1, 1);
    ls1 += __shfl_xor_sync(0xffffffffu, ls1, 2);
    if ((lane & 3) == 0) {
        lbuf[cn][rm * 16 + (lane >> 2)]     = ls0;
        lbuf[cn][rm * 16 + (lane >> 2) + 8] = ls1;
    }
    __syncthreads();   // also: all KV smem reads done before obuf aliasing

    // ---- merge O partials through smem (aliased over KV ring) ---------------
    float* obuf = (float*)smraw;   // [2][64][LSO] fp32 = 36864 B
    {
        int r0 = rm * 16 + (lane >> 2);
        int c0 = (lane & 3) * 2;
        float* ob = obuf + cn * 64 * LSO;
        #pragma unroll
        for (int n = 0; n < 8; n++) {
            float2 lo; lo.x = oacc[n][0]; lo.y = oacc[n][1];
            float2 hi; hi.x = oacc[n][2]; hi.y = oacc[n][3];
            *(float2*)&ob[r0 * LSO + n * 8 + c0]       = lo;
            *(float2*)&ob[(r0 + 8) * LSO + n * 8 + c0] = hi;
        }
    }
    __syncthreads();

    // ---- normalize + split-write ctx fp16 hi/lo -----------------------------
    {
        const float inv = 1.0f / (lbuf[0][row] + lbuf[1][row]);
        __half* chp = Chg + gbase;
        __half* clp = Clg + gbase;
        #pragma unroll
        for (int g = 0; g < 2; g++) {
            float v[8];
            #pragma unroll
            for (int e = 0; e < 8; e++) {
                int cc = cseg + g * 8 + e;
                v[e] = (obuf[row * LSO + cc] + obuf[64 * LSO + row * LSO + cc]) * inv;
            }
            uint4 hv, lv;
            split2h(v[0], v[1], hv.x, lv.x);
            split2h(v[2], v[3], hv.y, lv.y);
            split2h(v[4], v[5], hv.z, lv.z);
            split2h(v[6], v[7], hv.w, lv.w);
            *(uint4*)(chp + g * 8) = hv;
            *(uint4*)(clp + g * 8) = lv;
        }
    }
}

// ---------------------------------------------------------------------------
extern "C" void kernel_launch(void* const* d_in, const int* in_sizes, int n_in,
                              void* d_out, int out_size)
{
    const float* queries = (const float*)d_in[0];
    const float* keys    = (const float*)d_in[1];
    const float* values  = (const float*)d_in[2];
    const float* Wq      = (const float*)d_in[3];
    const float* Wk      = (const float*)d_in[4];
    const float* Wv      = (const float*)d_in[5];
    const float* Wo      = (const float*)d_in[6];
    float* out = (float*)d_out;

    __half *iqh,*iql,*ikh,*ikl,*ivh,*ivl;
    __half *wq,*wk,*wv,*wo;
    __half *Qh,*Ql,*Kb,*Vb,*Ch,*Cl;
    cudaGetSymbolAddress((void**)&iqh, g_iqh); cudaGetSymbolAddress((void**)&iql, g_iql);
    cudaGetSymbolAddress((void**)&ikh, g_ikh); cudaGetSymbolAddress((void**)&ikl, g_ikl);
    cudaGetSymbolAddress((void**)&ivh, g_ivh); cudaGetSymbolAddress((void**)&ivl, g_ivl);
    cudaGetSymbolAddress((void**)&wq, g_wq); cudaGetSymbolAddress((void**)&wk, g_wk);
    cudaGetSymbolAddress((void**)&wv, g_wv); cudaGetSymbolAddress((void**)&wo, g_wo);
    cudaGetSymbolAddress((void**)&Qh, g_Qh); cudaGetSymbolAddress((void**)&Ql, g_Ql);
    cudaGetSymbolAddress((void**)&Kb, g_K);  cudaGetSymbolAddress((void**)&Vb, g_V);
    cudaGetSymbolAddress((void**)&Ch, g_Ch); cudaGetSymbolAddress((void**)&Cl, g_Cl);

    cudaFuncSetAttribute(gemm_qkv, cudaFuncAttributeMaxDynamicSharedMemorySize, GEMM_SMEM);
    cudaFuncSetAttribute(gemm_wo,  cudaFuncAttributeMaxDynamicSharedMemorySize, GEMM_SMEM);
    cudaFuncSetAttribute(attn_mma, cudaFuncAttributeMaxDynamicSharedMemorySize, ATTN_SMEM);

    // ---- fused prep (3 splits + 4 converts), MLP=4 ----
    Prep p;
    p.src[0] = (const float4*)queries; p.h[0] = (uint2*)iqh; p.l[0] = (uint2*)iql;
    p.src[1] = (const float4*)keys;    p.h[1] = (uint2*)ikh; p.l[1] = (uint2*)ikl;
    p.src[2] = (const float4*)values;  p.h[2] = (uint2*)ivh; p.l[2] = (uint2*)ivl;
    p.src[3] = (const float4*)Wq; p.h[3] = (uint2*)wq; p.l[3] = nullptr;
    p.src[4] = (const float4*)Wk; p.h[4] = (uint2*)wk; p.l[4] = nullptr;
    p.src[5] = (const float4*)Wv; p.h[5] = (uint2*)wv; p.l[5] = nullptr;
    p.src[6] = (const float4*)Wo; p.h[6] = (uint2*)wo; p.l[6] = nullptr;
    prep_all<<<4096, 256>>>(p);

    // ---- fused QKV projection ----
    G3 g;
    g.Ah[0] = iqh; g.Al[0] = iql; g.Bw[0] = wq; g.C1[0] = Qh; g.C2[0] = Ql; g.alpha[0] = 0.125f;
    g.Ah[1] = ikh; g.Al[1] = ikl; g.Bw[1] = wk; g.C1[1] = Kb; g.C2[1] = nullptr; g.alpha[1] = 1.0f;
    g.Ah[2] = ivh; g.Al[2] = ivl; g.Bw[2] = wv; g.C1[2] = Vb; g.C2[2] = nullptr; g.alpha[2] = 1.0f;

    gemm_qkv<<<dim3(DD / 128, MROWS / 128, 3), 256, GEMM_SMEM>>>(g);

    attn_mma<<<dim3(SS / 64, HH, BB), 256, ATTN_SMEM>>>(Qh, Ql, Kb, Vb, Ch, Cl);

    gemm_wo<<<dim3(DD / 128, MROWS / 128), 256, GEMM_SMEM>>>(Ch, Cl, wo, out);
}

// round 15
// speedup vs baseline: 2.2058x; 1.0008x over previous
#include <cuda_runtime.h>
#include <cuda_fp16.h>
#include <mma.h>
#include <math.h>
#include <stdint.h>

using namespace nvcuda;

// Problem constants
#define BB 2
#define SS 2048
#define DD 1024
#define HH 16
#define HD 64
#define MROWS (BB*SS)      // 4096
#define NELEM (BB*SS*DD)   // 4M
#define WELEM (DD*DD)      // 1M

// ---------------------------------------------------------------------------
// Global scratch: A-side tensors as fp16 hi/lo, B-side tensors single fp16.
// ---------------------------------------------------------------------------
__device__ __half g_iqh[NELEM], g_iql[NELEM];
__device__ __half g_ikh[NELEM], g_ikl[NELEM];
__device__ __half g_ivh[NELEM], g_ivl[NELEM];
__device__ __half g_wq[WELEM], g_wk[WELEM], g_wv[WELEM], g_wo[WELEM];
__device__ __half g_Qh[NELEM], g_Ql[NELEM];
__device__ __half g_K[NELEM];
__device__ __half g_V[NELEM];
__device__ __half g_Ch[NELEM], g_Cl[NELEM];

__device__ __forceinline__ void split2h(float x, float y, uint32_t& hi, uint32_t& lo) {
    __half2 h = __floats2half2_rn(x, y);
    float hx = __low2float(h), hy = __high2float(h);
    __half2 l = __floats2half2_rn(x - hx, y - hy);
    hi = *(uint32_t*)&h; lo = *(uint32_t*)&l;
}
__device__ __forceinline__ uint32_t pack2h(float x, float y) {
    __half2 h = __floats2half2_rn(x, y);
    return *(uint32_t*)&h;
}

__device__ __forceinline__ uint32_t smem_u32(const void* p) {
    uint32_t a;
    asm("{ .reg .u64 t; cvta.to.shared.u64 t, %1; cvt.u32.u64 %0, t; }"
        : "=r"(a) : "l"(p));
    return a;
}
__device__ __forceinline__ void cp16(uint32_t dst, const void* src) {
    asm volatile("cp.async.cg.shared.global [%0], [%1], 16;" :: "r"(dst), "l"(src));
}
__device__ __forceinline__ void ldsm_x4(uint32_t* r, uint32_t addr) {
    asm volatile("ldmatrix.sync.aligned.m8n8.x4.shared.b16 {%0,%1,%2,%3}, [%4];"
        : "=r"(r[0]), "=r"(r[1]), "=r"(r[2]), "=r"(r[3]) : "r"(addr));
}
__device__ __forceinline__ void ldsm_x4_t(uint32_t* r, uint32_t addr) {
    asm volatile("ldmatrix.sync.aligned.m8n8.x4.trans.shared.b16 {%0,%1,%2,%3}, [%4];"
        : "=r"(r[0]), "=r"(r[1]), "=r"(r[2]), "=r"(r[3]) : "r"(addr));
}
__device__ __forceinline__ void mma16816(float* c, const uint32_t* a, uint32_t b0, uint32_t b1) {
    asm volatile(
        "mma.sync.aligned.m16n8k16.row.col.f32.f16.f16.f32 "
        "{%0,%1,%2,%3}, {%4,%5,%6,%7}, {%8,%9}, {%0,%1,%2,%3};"
        : "+f"(c[0]), "+f"(c[1]), "+f"(c[2]), "+f"(c[3])
        : "r"(a[0]), "r"(a[1]), "r"(a[2]), "r"(a[3]), "r"(b0), "r"(b1));
}

// ===========================================================================
// Fused prep with MLP=4: each thread handles 4 independent float4.
// Segments: [0,3): inputs (split hi/lo), 1024 blocks each;
//           [3,7): weights (convert),     256 blocks each.  Total 4096 blocks.
// ===========================================================================
struct Prep {
    const float4* src[7];
    uint2* h[7];
    uint2* l[7];
};

__global__ __launch_bounds__(256) void prep_all(Prep p)
{
    int blk = blockIdx.x;
    int seg, ib;
    if (blk < 3072) { seg = blk >> 10; ib = blk & 1023; }
    else { int r = blk - 3072; seg = 3 + (r >> 8); ib = r & 255; }
    const float4* src = p.src[seg];
    uint2* hp = p.h[seg];
    uint2* lp = p.l[seg];
    int i0 = ib * 1024 + threadIdx.x;

    float4 v[4];
    #pragma unroll
    for (int j = 0; j < 4; j++) v[j] = src[i0 + j * 256];   // 4 loads in flight

    if (seg < 3) {
        #pragma unroll
        for (int j = 0; j < 4; j++) {
            __half2 h0 = __floats2half2_rn(v[j].x, v[j].y);
            __half2 h1 = __floats2half2_rn(v[j].z, v[j].w);
            uint2 hh; hh.x = *(uint32_t*)&h0; hh.y = *(uint32_t*)&h1;
            hp[i0 + j * 256] = hh;
            __half2 l0 = __floats2half2_rn(v[j].x - __low2float(h0), v[j].y - __high2float(h0));
            __half2 l1 = __floats2half2_rn(v[j].z - __low2float(h1), v[j].w - __high2float(h1));
            uint2 ll; ll.x = *(uint32_t*)&l0; ll.y = *(uint32_t*)&l1;
            lp[i0 + j * 256] = ll;
        }
    } else {
        #pragma unroll
        for (int j = 0; j < 4; j++) {
            __half2 h0 = __floats2half2_rn(v[j].x, v[j].y);
            __half2 h1 = __floats2half2_rn(v[j].z, v[j].w);
            uint2 hh; hh.x = *(uint32_t*)&h0; hh.y = *(uint32_t*)&h1;
            hp[i0 + j * 256] = hh;
        }
    }
}

// ===========================================================================
// 2-term GEMM: C = alpha * (Ah + Al) @ B. 3-stage ring, ONE sync per chunk.
// 128x128 tile, BK=32, 8 warps (4x2), warp tile 32x64.
// ===========================================================================
#define BK 32
#define NC (DD / BK)       // 32
#define LDAs 40
#define LDBs 136
#define STG_A (128 * LDAs)           // 5120 halves
#define STG_B (BK * LDBs)            // 4352 halves
#define OFF_AL (STG_A * 2)
#define OFF_B  (2 * STG_A * 2)
#define STG_BYTES ((2 * STG_A + STG_B) * 2)   // 29184
#define GEMM_SMEM (3 * STG_BYTES)             // 87552 (>= 64KB epilogue staging)

__device__ __forceinline__ void issue_stage(
    uint32_t st, const __half* __restrict__ Ahg, const __half* __restrict__ Alg,
    const __half* __restrict__ Bg, int brow, int bcol, int k0, int tid)
{
    #pragma unroll
    for (int j = 0; j < 4; j++) {
        int c  = tid + 256 * j;
        const __half* Ag = (c < 512) ? Ahg : Alg;
        int c2 = c & 511;
        int r  = c2 >> 2;
        int q  = c2 & 3;
        uint32_t dst = st + ((c < 512) ? 0u : (uint32_t)OFF_AL)
                     + (uint32_t)r * (LDAs * 2) + (uint32_t)q * 16;
        cp16(dst, Ag + (size_t)(brow + r) * DD + k0 + q * 8);
    }
    #pragma unroll
    for (int j = 0; j < 2; j++) {
        int c  = tid + 256 * j;
        int kr = c >> 4;
        int cc = c & 15;
        uint32_t dst = st + OFF_B + (uint32_t)kr * (LDBs * 2) + (uint32_t)cc * 16;
        cp16(dst, Bg + (size_t)(k0 + kr) * DD + bcol + cc * 8);
    }
}

__device__ __forceinline__ void gemm_mainloop(
    char* smraw, uint32_t sb,
    const __half* __restrict__ Ahg, const __half* __restrict__ Alg,
    const __half* __restrict__ Bg,
    int brow, int bcol, int tid, int wm, int wn,
    wmma::fragment<wmma::accumulator, 16, 16, 16, float> (&acc)[2][4])
{
    #pragma unroll
    for (int i = 0; i < 2; i++)
        #pragma unroll
        for (int j = 0; j < 4; j++)
            wmma::fill_fragment(acc[i][j], 0.0f);

    issue_stage(sb, Ahg, Alg, Bg, brow, bcol, 0, tid);
    asm volatile("cp.async.commit_group;" ::: "memory");

    for (int c = 0; c < NC; c++) {
        const int st = c % 3;
        // S=3, d=1, one barrier/iter: issue(c+1) targets buf (c+1)%3 whose
        // readers were at iter c-2, protected by barrier(c-1).
        if (c + 1 < NC) {
            issue_stage(sb + (uint32_t)((c + 1) % 3) * STG_BYTES, Ahg, Alg, Bg,
                        brow, bcol, (c + 1) * BK, tid);
            asm volatile("cp.async.commit_group;" ::: "memory");
            asm volatile("cp.async.wait_group 1;" ::: "memory");
        } else {
            asm volatile("cp.async.wait_group 0;" ::: "memory");
        }
        __syncthreads();

        const __half* Ah = (const __half*)(smraw + st * STG_BYTES);
        const __half* Al = Ah + STG_A;
        const __half* Bs = Al + STG_A;

        #pragma unroll
        for (int ks = 0; ks < 2; ks++) {
            wmma::fragment<wmma::matrix_a, 16, 16, 16, __half, wmma::row_major> ah[2], al[2];
            wmma::fragment<wmma::matrix_b, 16, 16, 16, __half, wmma::row_major> bf[4];
            #pragma unroll
            for (int i = 0; i < 2; i++) {
                wmma::load_matrix_sync(ah[i], Ah + (wm * 32 + i * 16) * LDAs + ks * 16, LDAs);
                wmma::load_matrix_sync(al[i], Al + (wm * 32 + i * 16) * LDAs + ks * 16, LDAs);
            }
            #pragma unroll
            for (int j = 0; j < 4; j++)
                wmma::load_matrix_sync(bf[j], Bs + (ks * 16) * LDBs + wn * 64 + j * 16, LDBs);
            #pragma unroll
            for (int i = 0; i < 2; i++)
                #pragma unroll
                for (int j = 0; j < 4; j++) {
                    wmma::mma_sync(acc[i][j], ah[i], bf[j], acc[i][j]);
                    wmma::mma_sync(acc[i][j], al[i], bf[j], acc[i][j]);
                }
        }
        // no trailing sync (proof above)
    }
    __syncthreads();   // all smem reads done before epilogue aliases stages
}

// ---- fused Q/K/V projection: z=0 -> Q hi/lo, z=1 -> K single, z=2 -> V single
struct G3 {
    const __half *Ah[3], *Al[3], *Bw[3];
    __half *C1[3], *C2[3];
    float alpha[3];
};

__global__ __launch_bounds__(256, 2) void gemm_qkv(G3 g)
{
    extern __shared__ char smraw[];
    const uint32_t sb = smem_u32(smraw);
    const int tid  = threadIdx.x;
    const int wid  = tid >> 5;
    const int lane = tid & 31;
    const int wm   = wid & 3;
    const int wn   = wid >> 2;
    const int brow = blockIdx.y * 128;
    const int bcol = blockIdx.x * 128;
    const int z    = blockIdx.z;

    wmma::fragment<wmma::accumulator, 16, 16, 16, float> acc[2][4];
    gemm_mainloop(smraw, sb, g.Ah[z], g.Al[z], g.Bw[z], brow, bcol, tid, wm, wn, acc);

    const float alpha = g.alpha[z];
    #pragma unroll
    for (int i = 0; i < 2; i++)
        #pragma unroll
        for (int j = 0; j < 4; j++)
            #pragma unroll
            for (int e = 0; e < acc[i][j].num_elements; e++)
                acc[i][j].x[e] *= alpha;

    float* ws = (float*)(smraw) + wid * 2048;
    #pragma unroll
    for (int i = 0; i < 2; i++)
        #pragma unroll
        for (int j = 0; j < 4; j++)
            wmma::store_matrix_sync(ws + i * 16 * 64 + j * 16, acc[i][j], 64, wmma::mem_row_major);
    __syncwarp();
    const float* src = ws + lane * 64;
    int grow = brow + wm * 32 + lane;
    size_t obase = (size_t)grow * DD + bcol + wn * 64;

    if (z == 0) {
        __half* chp = g.C1[0] + obase;
        __half* clp = g.C2[0] + obase;
        #pragma unroll
        for (int gg = 0; gg < 8; gg++) {
            uint4 hv, lv;
            split2h(src[8 * gg + 0], src[8 * gg + 1], hv.x, lv.x);
            split2h(src[8 * gg + 2], src[8 * gg + 3], hv.y, lv.y);
            split2h(src[8 * gg + 4], src[8 * gg + 5], hv.z, lv.z);
            split2h(src[8 * gg + 6], src[8 * gg + 7], hv.w, lv.w);
            *(uint4*)(chp + 8 * gg) = hv;
            *(uint4*)(clp + 8 * gg) = lv;
        }
    } else {
        __half* cp = g.C1[z] + obase;
        #pragma unroll
        for (int gg = 0; gg < 8; gg++) {
            uint4 hv;
            hv.x = pack2h(src[8 * gg + 0], src[8 * gg + 1]);
            hv.y = pack2h(src[8 * gg + 2], src[8 * gg + 3]);
            hv.z = pack2h(src[8 * gg + 4], src[8 * gg + 5]);
            hv.w = pack2h(src[8 * gg + 6], src[8 * gg + 7]);
            *(uint4*)(cp + 8 * gg) = hv;
        }
    }
}

__global__ __launch_bounds__(256, 2) void gemm_wo(
    const __half* __restrict__ Ahg, const __half* __restrict__ Alg,
    const __half* __restrict__ Bg, float* __restrict__ Cf)
{
    extern __shared__ char smraw[];
    const uint32_t sb = smem_u32(smraw);
    const int tid  = threadIdx.x;
    const int wid  = tid >> 5;
    const int wm   = wid & 3;
    const int wn   = wid >> 2;
    const int brow = blockIdx.y * 128;
    const int bcol = blockIdx.x * 128;

    wmma::fragment<wmma::accumulator, 16, 16, 16, float> acc[2][4];
    gemm_mainloop(smraw, sb, Ahg, Alg, Bg, brow, bcol, tid, wm, wn, acc);

    #pragma unroll
    for (int i = 0; i < 2; i++)
        #pragma unroll
        for (int j = 0; j < 4; j++) {
            float* Cp = Cf + (size_t)(brow + wm * 32 + i * 16) * DD + bcol + wn * 64 + j * 16;
            wmma::store_matrix_sync(Cp, acc[i][j], DD, wmma::mem_row_major);
        }
}

// ===========================================================================
// Raw-mma flash attention: Q hi/lo (A-side), K/V single fp16 (B-side).
// 4-stage KV ring, prefetch distance 2, ONE sync per iteration.
// ===========================================================================
#define LQ  72
#define LSO 72
#define KVB_BYTES (2 * 64 * LQ * 2)   // K + V per buffer = 18432 B
#define ATTN_SMEM (4 * KVB_BYTES)     // 73728 (>= 36864 epilogue obuf)

__global__ __launch_bounds__(256, 2) void attn_mma(
    const __half* __restrict__ Qhg, const __half* __restrict__ Qlg,
    const __half* __restrict__ Kg,  const __half* __restrict__ Vg,
    __half* __restrict__ Chg, __half* __restrict__ Clg)
{
    extern __shared__ char smraw[];
    __half* KVs = (__half*)smraw;
    __shared__ float lbuf[2][64];

    const int tid  = threadIdx.x;
    const int lane = tid & 31;
    const int wid  = tid >> 5;
    const int rm   = wid >> 1;
    const int cn   = wid & 1;
    const int q0   = blockIdx.x * 64;
    const int h    = blockIdx.y;
    const int b    = blockIdx.z;
    const int row  = tid >> 2;
    const int cseg = (tid & 3) * 16;
    const size_t hoff = (size_t)h * HD;
    const size_t gbase = ((size_t)(b * SS) + q0 + row) * DD + hoff + cseg;

    const uint32_t base = smem_u32(KVs);
    const int rA = lane & 15, cA = (lane >> 4) * 8;
    const int rK = (lane & 7) + ((lane & 16) >> 1), cK = lane & 8;

    // KV tile issue for buffer `buf` (K at +0, V at +64*LQ*2), 4 cp16/thread
    auto issue_kv = [&](int buf, int kv0) {
        const size_t kb = ((size_t)(b * SS) + kv0 + row) * DD + hoff + cseg;
        uint32_t bb = base + (uint32_t)buf * KVB_BYTES + (uint32_t)(row * LQ + cseg) * 2;
        cp16(bb,      Kg + kb);
        cp16(bb + 16, Kg + kb + 8);
        cp16(bb + 64 * LQ * 2,      Vg + kb);
        cp16(bb + 64 * LQ * 2 + 16, Vg + kb + 8);
    };

    // ---- prologue: stage Q in buf3, prefetch chunks 0,1 ------------------
    {
        int bi = row * LQ + cseg;
        __half* q3 = KVs + 3 * (KVB_BYTES / 2);
        *(uint4*)&q3[bi]               = *(const uint4*)(Qhg + gbase);
        *(uint4*)&q3[bi + 8]           = *(const uint4*)(Qhg + gbase + 8);
        *(uint4*)&q3[64 * LQ + bi]     = *(const uint4*)(Qlg + gbase);
        *(uint4*)&q3[64 * LQ + bi + 8] = *(const uint4*)(Qlg + gbase + 8);
    }
    issue_kv(0, 0);
    asm volatile("cp.async.commit_group;" ::: "memory");
    issue_kv(1, 64);
    asm volatile("cp.async.commit_group;" ::: "memory");
    __syncthreads();   // Q generic stores visible

    uint32_t qh[4][4], ql[4][4];
    #pragma unroll
    for (int d = 0; d < 4; d++) {
        uint32_t a = base + 3u * KVB_BYTES
                   + (uint32_t)((rm * 16 + rA) * LQ + d * 16 + cA) * 2;
        ldsm_x4(qh[d], a);
        ldsm_x4(ql[d], a + 64 * LQ * 2);
    }
    __syncthreads();   // Q frag reads done before buf3 is reused (iter 1 issue)

    float oacc[8][4];
    #pragma unroll
    for (int n = 0; n < 8; n++)
        #pragma unroll
        for (int e = 0; e < 4; e++) oacc[n][e] = 0.0f;
    float ls0 = 0.0f, ls1 = 0.0f;

    for (int c = 0; c < SS / 64; c++) {
        // S=4, d=2, one barrier/iter: issue(c+2) targets buf (c+2)%4 whose
        // readers were at iter c-2, protected by barrier(c-1).
        if (c + 2 < SS / 64) {
            issue_kv((c + 2) & 3, (c + 2) * 64);
            asm volatile("cp.async.commit_group;" ::: "memory");
            asm volatile("cp.async.wait_group 2;" ::: "memory");
        } else if (c + 1 < SS / 64) {
            asm volatile("cp.async.wait_group 1;" ::: "memory");
        } else {
            asm volatile("cp.async.wait_group 0;" ::: "memory");
        }
        __syncthreads();

        const uint32_t bb = base + (uint32_t)(c & 3) * KVB_BYTES;

        // ---- S = Q @ K^T (2-term) --------------------------------------
        float s[4][4];
        #pragma unroll
        for (int j = 0; j < 4; j++)
            #pragma unroll
            for (int e = 0; e < 4; e++) s[j][e] = 0.0f;

        #pragma unroll
        for (int d = 0; d < 4; d++) {
            #pragma unroll
            for (int jp = 0; jp < 2; jp++) {
                uint32_t kf[4];
                uint32_t a = bb + (uint32_t)((cn * 32 + jp * 16 + rK) * LQ + d * 16 + cK) * 2;
                ldsm_x4(kf, a);
                mma16816(s[jp * 2],     qh[d], kf[0], kf[1]);
                mma16816(s[jp * 2],     ql[d], kf[0], kf[1]);
                mma16816(s[jp * 2 + 1], qh[d], kf[2], kf[3]);
                mma16816(s[jp * 2 + 1], ql[d], kf[2], kf[3]);
            }
        }

        // ---- exp + row-sum ----------------------------------------------
        #pragma unroll
        for (int j = 0; j < 4; j++) {
            s[j][0] = __expf(s[j][0]); s[j][1] = __expf(s[j][1]);
            s[j][2] = __expf(s[j][2]); s[j][3] = __expf(s[j][3]);
            ls0 += s[j][0] + s[j][1];
            ls1 += s[j][2] + s[j][3];
        }

        // ---- repack P -> fp16 hi/lo A fragments (register-only) ----------
        uint32_t ph[2][4], pl[2][4];
        #pragma unroll
        for (int kk = 0; kk < 2; kk++) {
            int j0 = kk * 2;
            split2h(s[j0][0],     s[j0][1],     ph[kk][0], pl[kk][0]);
            split2h(s[j0][2],     s[j0][3],     ph[kk][1], pl[kk][1]);
            split2h(s[j0 + 1][0], s[j0 + 1][1], ph[kk][2], pl[kk][2]);
            split2h(s[j0 + 1][2], s[j0 + 1][3], ph[kk][3], pl[kk][3]);
        }

        // ---- O_partial += P @ V (2-term) ----------------------------------
        #pragma unroll
        for (int kk = 0; kk < 2; kk++) {
            #pragma unroll
            for (int np = 0; np < 4; np++) {
                uint32_t vf[4];
                uint32_t a = bb + (uint32_t)(64 * LQ * 2)
                           + (uint32_t)((cn * 32 + kk * 16 + rA) * LQ + np * 16 + cA) * 2;
                ldsm_x4_t(vf, a);
                mma16816(oacc[np * 2],     ph[kk], vf[0], vf[1]);
                mma16816(oacc[np * 2],     pl[kk], vf[0], vf[1]);
                mma16816(oacc[np * 2 + 1], ph[kk], vf[2], vf[3]);
                mma16816(oacc[np * 2 + 1], pl[kk], vf[2], vf[3]);
            }
        }
        // no trailing sync (proof above)
    }

    // ---- row-sum halves ----------------------------------------------------
    ls0 += __shfl_xor_sync(0xffffffffu, ls0, 1);
    ls0 += __shfl_xor_sync(0xffffffffu, ls0, 2);
    ls1 += __shfl_xor_sync(0xffffffffu, ls1, 1);
    ls1 += __shfl_xor_sync(0xffffffffu, ls1, 2);
    if ((lane & 3) == 0) {
        lbuf[cn][rm * 16 + (lane >> 2)]     = ls0;
        lbuf[cn][rm * 16 + (lane >> 2) + 8] = ls1;
    }
    __syncthreads();   // also: all KV smem reads done before obuf aliasing

    // ---- merge O partials through smem (aliased over KV ring) ---------------
    float* obuf = (float*)smraw;   // [2][64][LSO] fp32 = 36864 B
    {
        int r0 = rm * 16 + (lane >> 2);
        int c0 = (lane & 3) * 2;
        float* ob = obuf + cn * 64 * LSO;
        #pragma unroll
        for (int n = 0; n < 8; n++) {
            float2 lo; lo.x = oacc[n][0]; lo.y = oacc[n][1];
            float2 hi; hi.x = oacc[n][2]; hi.y = oacc[n][3];
            *(float2*)&ob[r0 * LSO + n * 8 + c0]       = lo;
            *(float2*)&ob[(r0 + 8) * LSO + n * 8 + c0] = hi;
        }
    }
    __syncthreads();

    // ---- normalize + split-write ctx fp16 hi/lo -----------------------------
    {
        const float inv = 1.0f / (lbuf[0][row] + lbuf[1][row]);
        __half* chp = Chg + gbase;
        __half* clp = Clg + gbase;
        #pragma unroll
        for (int g = 0; g < 2; g++) {
            float v[8];
            #pragma unroll
            for (int e = 0; e < 8; e++) {
                int cc = cseg + g * 8 + e;
                v[e] = (obuf[row * LSO + cc] + obuf[64 * LSO + row * LSO + cc]) * inv;
            }
            uint4 hv, lv;
            split2h(v[0], v[1], hv.x, lv.x);
            split2h(v[2], v[3], hv.y, lv.y);
            split2h(v[4], v[5], hv.z, lv.z);
            split2h(v[6], v[7], hv.w, lv.w);
            *(uint4*)(chp + g * 8) = hv;
            *(uint4*)(clp + g * 8) = lv;
        }
    }
}

// ---------------------------------------------------------------------------
extern "C" void kernel_launch(void* const* d_in, const int* in_sizes, int n_in,
                              void* d_out, int out_size)
{
    const float* queries = (const float*)d_in[0];
    const float* keys    = (const float*)d_in[1];
    const float* values  = (const float*)d_in[2];
    const float* Wq      = (const float*)d_in[3];
    const float* Wk      = (const float*)d_in[4];
    const float* Wv      = (const float*)d_in[5];
    const float* Wo      = (const float*)d_in[6];
    float* out = (float*)d_out;

    __half *iqh,*iql,*ikh,*ikl,*ivh,*ivl;
    __half *wq,*wk,*wv,*wo;
    __half *Qh,*Ql,*Kb,*Vb,*Ch,*Cl;
    cudaGetSymbolAddress((void**)&iqh, g_iqh); cudaGetSymbolAddress((void**)&iql, g_iql);
    cudaGetSymbolAddress((void**)&ikh, g_ikh); cudaGetSymbolAddress((void**)&ikl, g_ikl);
    cudaGetSymbolAddress((void**)&ivh, g_ivh); cudaGetSymbolAddress((void**)&ivl, g_ivl);
    cudaGetSymbolAddress((void**)&wq, g_wq); cudaGetSymbolAddress((void**)&wk, g_wk);
    cudaGetSymbolAddress((void**)&wv, g_wv); cudaGetSymbolAddress((void**)&wo, g_wo);
    cudaGetSymbolAddress((void**)&Qh, g_Qh); cudaGetSymbolAddress((void**)&Ql, g_Ql);
    cudaGetSymbolAddress((void**)&Kb, g_K);  cudaGetSymbolAddress((void**)&Vb, g_V);
    cudaGetSymbolAddress((void**)&Ch, g_Ch); cudaGetSymbolAddress((void**)&Cl, g_Cl);

    cudaFuncSetAttribute(gemm_qkv, cudaFuncAttributeMaxDynamicSharedMemorySize, GEMM_SMEM);
    cudaFuncSetAttribute(gemm_wo,  cudaFuncAttributeMaxDynamicSharedMemorySize, GEMM_SMEM);
    cudaFuncSetAttribute(attn_mma, cudaFuncAttributeMaxDynamicSharedMemorySize, ATTN_SMEM);

    // ---- fused prep (3 splits + 4 converts), MLP=4 ----
    Prep p;
    p.src[0] = (const float4*)queries; p.h[0] = (uint2*)iqh; p.l[0] = (uint2*)iql;
    p.src[1] = (const float4*)keys;    p.h[1] = (uint2*)ikh; p.l[1] = (uint2*)ikl;
    p.src[2] = (const float4*)values;  p.h[2] = (uint2*)ivh; p.l[2] = (uint2*)ivl;
    p.src[3] = (const float4*)Wq; p.h[3] = (uint2*)wq; p.l[3] = nullptr;
    p.src[4] = (const float4*)Wk; p.h[4] = (uint2*)wk; p.l[4] = nullptr;
    p.src[5] = (const float4*)Wv; p.h[5] = (uint2*)wv; p.l[5] = nullptr;
    p.src[6] = (const float4*)Wo; p.h[6] = (uint2*)wo; p.l[6] = nullptr;
    prep_all<<<4096, 256>>>(p);

    // ---- fused QKV projection ----
    G3 g;
    g.Ah[0] = iqh; g.Al[0] = iql; g.Bw[0] = wq; g.C1[0] = Qh; g.C2[0] = Ql; g.alpha[0] = 0.125f;
    g.Ah[1] = ikh; g.Al[1] = ikl; g.Bw[1] = wk; g.C1[1] = Kb; g.C2[1] = nullptr; g.alpha[1] = 1.0f;
    g.Ah[2] = ivh; g.Al[2] = ivl; g.Bw[2] = wv; g.C1[2] = Vb; g.C2[2] = nullptr; g.alpha[2] = 1.0f;

    gemm_qkv<<<dim3(DD / 128, MROWS / 128, 3), 256, GEMM_SMEM>>>(g);

    attn_mma<<<dim3(SS / 64, HH, BB), 256, ATTN_SMEM>>>(Qh, Ql, Kb, Vb, Ch, Cl);

    gemm_wo<<<dim3(DD / 128, MROWS / 128), 256, GEMM_SMEM>>>(Ch, Cl, wo, out);
}

// round 16
// speedup vs baseline: 2.2065x; 1.0003x over previous
#include <cuda_runtime.h>
#include <cuda_fp16.h>
#include <mma.h>
#include <math.h>
#include <stdint.h>

using namespace nvcuda;

// Problem constants
#define BB 2
#define SS 2048
#define DD 1024
#define HH 16
#define HD 64
#define MROWS (BB*SS)      // 4096
#define NELEM (BB*SS*DD)   // 4M
#define WELEM (DD*DD)      // 1M

// ---------------------------------------------------------------------------
// Global scratch: A-side tensors as fp16 hi/lo, B-side tensors single fp16.
// ---------------------------------------------------------------------------
__device__ __half g_iqh[NELEM], g_iql[NELEM];
__device__ __half g_ikh[NELEM], g_ikl[NELEM];
__device__ __half g_ivh[NELEM], g_ivl[NELEM];
__device__ __half g_wq[WELEM], g_wk[WELEM], g_wv[WELEM], g_wo[WELEM];
__device__ __half g_Qh[NELEM], g_Ql[NELEM];
__device__ __half g_K[NELEM];
__device__ __half g_V[NELEM];
__device__ __half g_Ch[NELEM], g_Cl[NELEM];

__device__ __forceinline__ void split2h(float x, float y, uint32_t& hi, uint32_t& lo) {
    __half2 h = __floats2half2_rn(x, y);
    float hx = __low2float(h), hy = __high2float(h);
    __half2 l = __floats2half2_rn(x - hx, y - hy);
    hi = *(uint32_t*)&h; lo = *(uint32_t*)&l;
}
__device__ __forceinline__ uint32_t pack2h(float x, float y) {
    __half2 h = __floats2half2_rn(x, y);
    return *(uint32_t*)&h;
}

__device__ __forceinline__ uint32_t smem_u32(const void* p) {
    uint32_t a;
    asm("{ .reg .u64 t; cvta.to.shared.u64 t, %1; cvt.u32.u64 %0, t; }"
        : "=r"(a) : "l"(p));
    return a;
}
__device__ __forceinline__ void cp16(uint32_t dst, const void* src) {
    asm volatile("cp.async.cg.shared.global [%0], [%1], 16;" :: "r"(dst), "l"(src));
}
__device__ __forceinline__ void ldsm_x4(uint32_t* r, uint32_t addr) {
    asm volatile("ldmatrix.sync.aligned.m8n8.x4.shared.b16 {%0,%1,%2,%3}, [%4];"
        : "=r"(r[0]), "=r"(r[1]), "=r"(r[2]), "=r"(r[3]) : "r"(addr));
}
__device__ __forceinline__ void ldsm_x4_t(uint32_t* r, uint32_t addr) {
    asm volatile("ldmatrix.sync.aligned.m8n8.x4.trans.shared.b16 {%0,%1,%2,%3}, [%4];"
        : "=r"(r[0]), "=r"(r[1]), "=r"(r[2]), "=r"(r[3]) : "r"(addr));
}
__device__ __forceinline__ void mma16816(float* c, const uint32_t* a, uint32_t b0, uint32_t b1) {
    asm volatile(
        "mma.sync.aligned.m16n8k16.row.col.f32.f16.f16.f32 "
        "{%0,%1,%2,%3}, {%4,%5,%6,%7}, {%8,%9}, {%0,%1,%2,%3};"
        : "+f"(c[0]), "+f"(c[1]), "+f"(c[2]), "+f"(c[3])
        : "r"(a[0]), "r"(a[1]), "r"(a[2]), "r"(a[3]), "r"(b0), "r"(b1));
}

// ===========================================================================
// Fused prep with MLP=4: each thread handles 4 independent float4.
// Segments: [0,3): inputs (split hi/lo), 1024 blocks each;
//           [3,7): weights (convert),     256 blocks each.  Total 4096 blocks.
// ===========================================================================
struct Prep {
    const float4* src[7];
    uint2* h[7];
    uint2* l[7];
};

__global__ __launch_bounds__(256) void prep_all(Prep p)
{
    int blk = blockIdx.x;
    int seg, ib;
    if (blk < 3072) { seg = blk >> 10; ib = blk & 1023; }
    else { int r = blk - 3072; seg = 3 + (r >> 8); ib = r & 255; }
    const float4* src = p.src[seg];
    uint2* hp = p.h[seg];
    uint2* lp = p.l[seg];
    int i0 = ib * 1024 + threadIdx.x;

    float4 v[4];
    #pragma unroll
    for (int j = 0; j < 4; j++) v[j] = src[i0 + j * 256];   // 4 loads in flight

    if (seg < 3) {
        #pragma unroll
        for (int j = 0; j < 4; j++) {
            __half2 h0 = __floats2half2_rn(v[j].x, v[j].y);
            __half2 h1 = __floats2half2_rn(v[j].z, v[j].w);
            uint2 hh; hh.x = *(uint32_t*)&h0; hh.y = *(uint32_t*)&h1;
            hp[i0 + j * 256] = hh;
            __half2 l0 = __floats2half2_rn(v[j].x - __low2float(h0), v[j].y - __high2float(h0));
            __half2 l1 = __floats2half2_rn(v[j].z - __low2float(h1), v[j].w - __high2float(h1));
            uint2 ll; ll.x = *(uint32_t*)&l0; ll.y = *(uint32_t*)&l1;
            lp[i0 + j * 256] = ll;
        }
    } else {
        #pragma unroll
        for (int j = 0; j < 4; j++) {
            __half2 h0 = __floats2half2_rn(v[j].x, v[j].y);
            __half2 h1 = __floats2half2_rn(v[j].z, v[j].w);
            uint2 hh; hh.x = *(uint32_t*)&h0; hh.y = *(uint32_t*)&h1;
            hp[i0 + j * 256] = hh;
        }
    }
}

// ===========================================================================
// 2-term GEMM: C = alpha * (Ah + Al) @ B. 3-stage ring, ONE sync per chunk.
// 128x128 tile, BK=32, 8 warps (4x2), warp tile 32x64.
// ===========================================================================
#define BK 32
#define NC (DD / BK)       // 32
#define LDAs 40
#define LDBs 136
#define STG_A (128 * LDAs)           // 5120 halves
#define STG_B (BK * LDBs)            // 4352 halves
#define OFF_AL (STG_A * 2)
#define OFF_B  (2 * STG_A * 2)
#define STG_BYTES ((2 * STG_A + STG_B) * 2)   // 29184
#define GEMM_SMEM (3 * STG_BYTES)             // 87552 (>= 64KB epilogue staging)

__device__ __forceinline__ void issue_stage(
    uint32_t st, const __half* __restrict__ Ahg, const __half* __restrict__ Alg,
    const __half* __restrict__ Bg, int brow, int bcol, int k0, int tid)
{
    #pragma unroll
    for (int j = 0; j < 4; j++) {
        int c  = tid + 256 * j;
        const __half* Ag = (c < 512) ? Ahg : Alg;
        int c2 = c & 511;
        int r  = c2 >> 2;
        int q  = c2 & 3;
        uint32_t dst = st + ((c < 512) ? 0u : (uint32_t)OFF_AL)
                     + (uint32_t)r * (LDAs * 2) + (uint32_t)q * 16;
        cp16(dst, Ag + (size_t)(brow + r) * DD + k0 + q * 8);
    }
    #pragma unroll
    for (int j = 0; j < 2; j++) {
        int c  = tid + 256 * j;
        int kr = c >> 4;
        int cc = c & 15;
        uint32_t dst = st + OFF_B + (uint32_t)kr * (LDBs * 2) + (uint32_t)cc * 16;
        cp16(dst, Bg + (size_t)(k0 + kr) * DD + bcol + cc * 8);
    }
}

__device__ __forceinline__ void gemm_mainloop(
    char* smraw, uint32_t sb,
    const __half* __restrict__ Ahg, const __half* __restrict__ Alg,
    const __half* __restrict__ Bg,
    int brow, int bcol, int tid, int wm, int wn,
    wmma::fragment<wmma::accumulator, 16, 16, 16, float> (&acc)[2][4])
{
    #pragma unroll
    for (int i = 0; i < 2; i++)
        #pragma unroll
        for (int j = 0; j < 4; j++)
            wmma::fill_fragment(acc[i][j], 0.0f);

    issue_stage(sb, Ahg, Alg, Bg, brow, bcol, 0, tid);
    asm volatile("cp.async.commit_group;" ::: "memory");

    for (int c = 0; c < NC; c++) {
        const int st = c % 3;
        // S=3, d=1, one barrier/iter: issue(c+1) targets buf (c+1)%3 whose
        // readers were at iter c-2, protected by barrier(c-1).
        if (c + 1 < NC) {
            issue_stage(sb + (uint32_t)((c + 1) % 3) * STG_BYTES, Ahg, Alg, Bg,
                        brow, bcol, (c + 1) * BK, tid);
            asm volatile("cp.async.commit_group;" ::: "memory");
            asm volatile("cp.async.wait_group 1;" ::: "memory");
        } else {
            asm volatile("cp.async.wait_group 0;" ::: "memory");
        }
        __syncthreads();

        const __half* Ah = (const __half*)(smraw + st * STG_BYTES);
        const __half* Al = Ah + STG_A;
        const __half* Bs = Al + STG_A;

        #pragma unroll
        for (int ks = 0; ks < 2; ks++) {
            wmma::fragment<wmma::matrix_a, 16, 16, 16, __half, wmma::row_major> ah[2], al[2];
            wmma::fragment<wmma::matrix_b, 16, 16, 16, __half, wmma::row_major> bf[4];
            #pragma unroll
            for (int i = 0; i < 2; i++) {
                wmma::load_matrix_sync(ah[i], Ah + (wm * 32 + i * 16) * LDAs + ks * 16, LDAs);
                wmma::load_matrix_sync(al[i], Al + (wm * 32 + i * 16) * LDAs + ks * 16, LDAs);
            }
            #pragma unroll
            for (int j = 0; j < 4; j++)
                wmma::load_matrix_sync(bf[j], Bs + (ks * 16) * LDBs + wn * 64 + j * 16, LDBs);
            #pragma unroll
            for (int i = 0; i < 2; i++)
                #pragma unroll
                for (int j = 0; j < 4; j++) {
                    wmma::mma_sync(acc[i][j], ah[i], bf[j], acc[i][j]);
                    wmma::mma_sync(acc[i][j], al[i], bf[j], acc[i][j]);
                }
        }
        // no trailing sync (proof above)
    }
    __syncthreads();   // all smem reads done before epilogue aliases stages
}

// ---- fused Q/K/V projection: z=0 -> Q hi/lo, z=1 -> K single, z=2 -> V single
struct G3 {
    const __half *Ah[3], *Al[3], *Bw[3];
    __half *C1[3], *C2[3];
    float alpha[3];
};

__global__ __launch_bounds__(256, 2) void gemm_qkv(G3 g)
{
    extern __shared__ char smraw[];
    const uint32_t sb = smem_u32(smraw);
    const int tid  = threadIdx.x;
    const int wid  = tid >> 5;
    const int lane = tid & 31;
    const int wm   = wid & 3;
    const int wn   = wid >> 2;
    const int brow = blockIdx.y * 128;
    const int bcol = blockIdx.x * 128;
    const int z    = blockIdx.z;

    wmma::fragment<wmma::accumulator, 16, 16, 16, float> acc[2][4];
    gemm_mainloop(smraw, sb, g.Ah[z], g.Al[z], g.Bw[z], brow, bcol, tid, wm, wn, acc);

    const float alpha = g.alpha[z];
    #pragma unroll
    for (int i = 0; i < 2; i++)
        #pragma unroll
        for (int j = 0; j < 4; j++)
            #pragma unroll
            for (int e = 0; e < acc[i][j].num_elements; e++)
                acc[i][j].x[e] *= alpha;

    float* ws = (float*)(smraw) + wid * 2048;
    #pragma unroll
    for (int i = 0; i < 2; i++)
        #pragma unroll
        for (int j = 0; j < 4; j++)
            wmma::store_matrix_sync(ws + i * 16 * 64 + j * 16, acc[i][j], 64, wmma::mem_row_major);
    __syncwarp();
    const float* src = ws + lane * 64;
    int grow = brow + wm * 32 + lane;
    size_t obase = (size_t)grow * DD + bcol + wn * 64;

    if (z == 0) {
        __half* chp = g.C1[0] + obase;
        __half* clp = g.C2[0] + obase;
        #pragma unroll
        for (int gg = 0; gg < 8; gg++) {
            uint4 hv, lv;
            split2h(src[8 * gg + 0], src[8 * gg + 1], hv.x, lv.x);
            split2h(src[8 * gg + 2], src[8 * gg + 3], hv.y, lv.y);
            split2h(src[8 * gg + 4], src[8 * gg + 5], hv.z, lv.z);
            split2h(src[8 * gg + 6], src[8 * gg + 7], hv.w, lv.w);
            *(uint4*)(chp + 8 * gg) = hv;
            *(uint4*)(clp + 8 * gg) = lv;
        }
    } else {
        __half* cp = g.C1[z] + obase;
        #pragma unroll
        for (int gg = 0; gg < 8; gg++) {
            uint4 hv;
            hv.x = pack2h(src[8 * gg + 0], src[8 * gg + 1]);
            hv.y = pack2h(src[8 * gg + 2], src[8 * gg + 3]);
            hv.z = pack2h(src[8 * gg + 4], src[8 * gg + 5]);
            hv.w = pack2h(src[8 * gg + 6], src[8 * gg + 7]);
            *(uint4*)(cp + 8 * gg) = hv;
        }
    }
}

__global__ __launch_bounds__(256, 2) void gemm_wo(
    const __half* __restrict__ Ahg, const __half* __restrict__ Alg,
    const __half* __restrict__ Bg, float* __restrict__ Cf)
{
    extern __shared__ char smraw[];
    const uint32_t sb = smem_u32(smraw);
    const int tid  = threadIdx.x;
    const int wid  = tid >> 5;
    const int wm   = wid & 3;
    const int wn   = wid >> 2;
    const int brow = blockIdx.y * 128;
    const int bcol = blockIdx.x * 128;

    wmma::fragment<wmma::accumulator, 16, 16, 16, float> acc[2][4];
    gemm_mainloop(smraw, sb, Ahg, Alg, Bg, brow, bcol, tid, wm, wn, acc);

    #pragma unroll
    for (int i = 0; i < 2; i++)
        #pragma unroll
        for (int j = 0; j < 4; j++) {
            float* Cp = Cf + (size_t)(brow + wm * 32 + i * 16) * DD + bcol + wn * 64 + j * 16;
            wmma::store_matrix_sync(Cp, acc[i][j], DD, wmma::mem_row_major);
        }
}

// ===========================================================================
// Raw-mma flash attention: Q hi/lo (A-side), K/V single fp16 (B-side).
// 4-stage KV ring, prefetch distance 2, ONE sync per iteration.
// ===========================================================================
#define LQ  72
#define LSO 72
#define KVB_BYTES (2 * 64 * LQ * 2)   // K + V per buffer = 18432 B
#define ATTN_SMEM (4 * KVB_BYTES)     // 73728 (>= 36864 epilogue obuf)

__global__ __launch_bounds__(256, 2) void attn_mma(
    const __half* __restrict__ Qhg, const __half* __restrict__ Qlg,
    const __half* __restrict__ Kg,  const __half* __restrict__ Vg,
    __half* __restrict__ Chg, __half* __restrict__ Clg)
{
    extern __shared__ char smraw[];
    __half* KVs = (__half*)smraw;
    __shared__ float lbuf[2][64];

    const int tid  = threadIdx.x;
    const int lane = tid & 31;
    const int wid  = tid >> 5;
    const int rm   = wid >> 1;
    const int cn   = wid & 1;
    const int q0   = blockIdx.x * 64;
    const int h    = blockIdx.y;
    const int b    = blockIdx.z;
    const int row  = tid >> 2;
    const int cseg = (tid & 3) * 16;
    const size_t hoff = (size_t)h * HD;
    const size_t gbase = ((size_t)(b * SS) + q0 + row) * DD + hoff + cseg;

    const uint32_t base = smem_u32(KVs);
    const int rA = lane & 15, cA = (lane >> 4) * 8;
    const int rK = (lane & 7) + ((lane & 16) >> 1), cK = lane & 8;

    // KV tile issue for buffer `buf` (K at +0, V at +64*LQ*2), 4 cp16/thread
    auto issue_kv = [&](int buf, int kv0) {
        const size_t kb = ((size_t)(b * SS) + kv0 + row) * DD + hoff + cseg;
        uint32_t bb = base + (uint32_t)buf * KVB_BYTES + (uint32_t)(row * LQ + cseg) * 2;
        cp16(bb,      Kg + kb);
        cp16(bb + 16, Kg + kb + 8);
        cp16(bb + 64 * LQ * 2,      Vg + kb);
        cp16(bb + 64 * LQ * 2 + 16, Vg + kb + 8);
    };

    // ---- prologue: stage Q in buf3, prefetch chunks 0,1 ------------------
    {
        int bi = row * LQ + cseg;
        __half* q3 = KVs + 3 * (KVB_BYTES / 2);
        *(uint4*)&q3[bi]               = *(const uint4*)(Qhg + gbase);
        *(uint4*)&q3[bi + 8]           = *(const uint4*)(Qhg + gbase + 8);
        *(uint4*)&q3[64 * LQ + bi]     = *(const uint4*)(Qlg + gbase);
        *(uint4*)&q3[64 * LQ + bi + 8] = *(const uint4*)(Qlg + gbase + 8);
    }
    issue_kv(0, 0);
    asm volatile("cp.async.commit_group;" ::: "memory");
    issue_kv(1, 64);
    asm volatile("cp.async.commit_group;" ::: "memory");
    __syncthreads();   // Q generic stores visible

    uint32_t qh[4][4], ql[4][4];
    #pragma unroll
    for (int d = 0; d < 4; d++) {
        uint32_t a = base + 3u * KVB_BYTES
                   + (uint32_t)((rm * 16 + rA) * LQ + d * 16 + cA) * 2;
        ldsm_x4(qh[d], a);
        ldsm_x4(ql[d], a + 64 * LQ * 2);
    }
    __syncthreads();   // Q frag reads done before buf3 is reused (iter 1 issue)

    float oacc[8][4];
    #pragma unroll
    for (int n = 0; n < 8; n++)
        #pragma unroll
        for (int e = 0; e < 4; e++) oacc[n][e] = 0.0f;
    float ls0 = 0.0f, ls1 = 0.0f;

    for (int c = 0; c < SS / 64; c++) {
        // S=4, d=2, one barrier/iter: issue(c+2) targets buf (c+2)%4 whose
        // readers were at iter c-2, protected by barrier(c-1).
        if (c + 2 < SS / 64) {
            issue_kv((c + 2) & 3, (c + 2) * 64);
            asm volatile("cp.async.commit_group;" ::: "memory");
            asm volatile("cp.async.wait_group 2;" ::: "memory");
        } else if (c + 1 < SS / 64) {
            asm volatile("cp.async.wait_group 1;" ::: "memory");
        } else {
            asm volatile("cp.async.wait_group 0;" ::: "memory");
        }
        __syncthreads();

        const uint32_t bb = base + (uint32_t)(c & 3) * KVB_BYTES;

        // ---- S = Q @ K^T (2-term) --------------------------------------
        float s[4][4];
        #pragma unroll
        for (int j = 0; j < 4; j++)
            #pragma unroll
            for (int e = 0; e < 4; e++) s[j][e] = 0.0f;

        #pragma unroll
        for (int d = 0; d < 4; d++) {
            #pragma unroll
            for (int jp = 0; jp < 2; jp++) {
                uint32_t kf[4];
                uint32_t a = bb + (uint32_t)((cn * 32 + jp * 16 + rK) * LQ + d * 16 + cK) * 2;
                ldsm_x4(kf, a);
                mma16816(s[jp * 2],     qh[d], kf[0], kf[1]);
                mma16816(s[jp * 2],     ql[d], kf[0], kf[1]);
                mma16816(s[jp * 2 + 1], qh[d], kf[2], kf[3]);
                mma16816(s[jp * 2 + 1], ql[d], kf[2], kf[3]);
            }
        }

        // ---- exp + row-sum ----------------------------------------------
        #pragma unroll
        for (int j = 0; j < 4; j++) {
            s[j][0] = __expf(s[j][0]); s[j][1] = __expf(s[j][1]);
            s[j][2] = __expf(s[j][2]); s[j][3] = __expf(s[j][3]);
            ls0 += s[j][0] + s[j][1];
            ls1 += s[j][2] + s[j][3];
        }

        // ---- repack P -> fp16 hi/lo A fragments (register-only) ----------
        uint32_t ph[2][4], pl[2][4];
        #pragma unroll
        for (int kk = 0; kk < 2; kk++) {
            int j0 = kk * 2;
            split2h(s[j0][0],     s[j0][1],     ph[kk][0], pl[kk][0]);
            split2h(s[j0][2],     s[j0][3],     ph[kk][1], pl[kk][1]);
            split2h(s[j0 + 1][0], s[j0 + 1][1], ph[kk][2], pl[kk][2]);
            split2h(s[j0 + 1][2], s[j0 + 1][3], ph[kk][3], pl[kk][3]);
        }

        // ---- O_partial += P @ V (2-term) ----------------------------------
        #pragma unroll
        for (int kk = 0; kk < 2; kk++) {
            #pragma unroll
            for (int np = 0; np < 4; np++) {
                uint32_t vf[4];
                uint32_t a = bb + (uint32_t)(64 * LQ * 2)
                           + (uint32_t)((cn * 32 + kk * 16 + rA) * LQ + np * 16 + cA) * 2;
                ldsm_x4_t(vf, a);
                mma16816(oacc[np * 2],     ph[kk], vf[0], vf[1]);
                mma16816(oacc[np * 2],     pl[kk], vf[0], vf[1]);
                mma16816(oacc[np * 2 + 1], ph[kk], vf[2], vf[3]);
                mma16816(oacc[np * 2 + 1], pl[kk], vf[2], vf[3]);
            }
        }
        // no trailing sync (proof above)
    }

    // ---- row-sum halves ----------------------------------------------------
    ls0 += __shfl_xor_sync(0xffffffffu, ls0, 1);
    ls0 += __shfl_xor_sync(0xffffffffu, ls0, 2);
    ls1 += __shfl_xor_sync(0xffffffffu, ls1, 1);
    ls1 += __shfl_xor_sync(0xffffffffu, ls1, 2);
    if ((lane & 3) == 0) {
        lbuf[cn][rm * 16 + (lane >> 2)]     = ls0;
        lbuf[cn][rm * 16 + (lane >> 2) + 8] = ls1;
    }
    __syncthreads();   // also: all KV smem reads done before obuf aliasing

    // ---- merge O partials through smem (aliased over KV ring) ---------------
    float* obuf = (float*)smraw;   // [2][64][LSO] fp32 = 36864 B
    {
        int r0 = rm * 16 + (lane >> 2);
        int c0 = (lane & 3) * 2;
        float* ob = obuf + cn * 64 * LSO;
        #pragma unroll
        for (int n = 0; n < 8; n++) {
            float2 lo; lo.x = oacc[n][0]; lo.y = oacc[n][1];
            float2 hi; hi.x = oacc[n][2]; hi.y = oacc[n][3];
            *(float2*)&ob[r0 * LSO + n * 8 + c0]       = lo;
            *(float2*)&ob[(r0 + 8) * LSO + n * 8 + c0] = hi;
        }
    }
    __syncthreads();

    // ---- normalize + split-write ctx fp16 hi/lo -----------------------------
    {
        const float inv = 1.0f / (lbuf[0][row] + lbuf[1][row]);
        __half* chp = Chg + gbase;
        __half* clp = Clg + gbase;
        #pragma unroll
        for (int g = 0; g < 2; g++) {
            float v[8];
            #pragma unroll
            for (int e = 0; e < 8; e++) {
                int cc = cseg + g * 8 + e;
                v[e] = (obuf[row * LSO + cc] + obuf[64 * LSO + row * LSO + cc]) * inv;
            }
            uint4 hv, lv;
            split2h(v[0], v[1], hv.x, lv.x);
            split2h(v[2], v[3], hv.y, lv.y);
            split2h(v[4], v[5], hv.z, lv.z);
            split2h(v[6], v[7], hv.w, lv.w);
            *(uint4*)(chp + g * 8) = hv;
            *(uint4*)(clp + g * 8) = lv;
        }
    }
}

// ---------------------------------------------------------------------------
extern "C" void kernel_launch(void* const* d_in, const int* in_sizes, int n_in,
                              void* d_out, int out_size)
{
    const float* queries = (const float*)d_in[0];
    const float* keys    = (const float*)d_in[1];
    const float* values  = (const float*)d_in[2];
    const float* Wq      = (const float*)d_in[3];
    const float* Wk      = (const float*)d_in[4];
    const float* Wv      = (const float*)d_in[5];
    const float* Wo      = (const float*)d_in[6];
    float* out = (float*)d_out;

    __half *iqh,*iql,*ikh,*ikl,*ivh,*ivl;
    __half *wq,*wk,*wv,*wo;
    __half *Qh,*Ql,*Kb,*Vb,*Ch,*Cl;
    cudaGetSymbolAddress((void**)&iqh, g_iqh); cudaGetSymbolAddress((void**)&iql, g_iql);
    cudaGetSymbolAddress((void**)&ikh, g_ikh); cudaGetSymbolAddress((void**)&ikl, g_ikl);
    cudaGetSymbolAddress((void**)&ivh, g_ivh); cudaGetSymbolAddress((void**)&ivl, g_ivl);
    cudaGetSymbolAddress((void**)&wq, g_wq); cudaGetSymbolAddress((void**)&wk, g_wk);
    cudaGetSymbolAddress((void**)&wv, g_wv); cudaGetSymbolAddress((void**)&wo, g_wo);
    cudaGetSymbolAddress((void**)&Qh, g_Qh); cudaGetSymbolAddress((void**)&Ql, g_Ql);
    cudaGetSymbolAddress((void**)&Kb, g_K);  cudaGetSymbolAddress((void**)&Vb, g_V);
    cudaGetSymbolAddress((void**)&Ch, g_Ch); cudaGetSymbolAddress((void**)&Cl, g_Cl);

    cudaFuncSetAttribute(gemm_qkv, cudaFuncAttributeMaxDynamicSharedMemorySize, GEMM_SMEM);
    cudaFuncSetAttribute(gemm_wo,  cudaFuncAttributeMaxDynamicSharedMemorySize, GEMM_SMEM);
    cudaFuncSetAttribute(attn_mma, cudaFuncAttributeMaxDynamicSharedMemorySize, ATTN_SMEM);

    // ---- fused prep (3 splits + 4 converts), MLP=4 ----
    Prep p;
    p.src[0] = (const float4*)queries; p.h[0] = (uint2*)iqh; p.l[0] = (uint2*)iql;
    p.src[1] = (const float4*)keys;    p.h[1] = (uint2*)ikh; p.l[1] = (uint2*)ikl;
    p.src[2] = (const float4*)values;  p.h[2] = (uint2*)ivh; p.l[2] = (uint2*)ivl;
    p.src[3] = (const float4*)Wq; p.h[3] = (uint2*)wq; p.l[3] = nullptr;
    p.src[4] = (const float4*)Wk; p.h[4] = (uint2*)wk; p.l[4] = nullptr;
    p.src[5] = (const float4*)Wv; p.h[5] = (uint2*)wv; p.l[5] = nullptr;
    p.src[6] = (const float4*)Wo; p.h[6] = (uint2*)wo; p.l[6] = nullptr;
    prep_all<<<4096, 256>>>(p);

    // ---- fused QKV projection ----
    G3 g;
    g.Ah[0] = iqh; g.Al[0] = iql; g.Bw[0] = wq; g.C1[0] = Qh; g.C2[0] = Ql; g.alpha[0] = 0.125f;
    g.Ah[1] = ikh; g.Al[1] = ikl; g.Bw[1] = wk; g.C1[1] = Kb; g.C2[1] = nullptr; g.alpha[1] = 1.0f;
    g.Ah[2] = ivh; g.Al[2] = ivl; g.Bw[2] = wv; g.C1[2] = Vb; g.C2[2] = nullptr; g.alpha[2] = 1.0f;

    gemm_qkv<<<dim3(DD / 128, MROWS / 128, 3), 256, GEMM_SMEM>>>(g);

    attn_mma<<<dim3(SS / 64, HH, BB), 256, ATTN_SMEM>>>(Qh, Ql, Kb, Vb, Ch, Cl);

    gemm_wo<<<dim3(DD / 128, MROWS / 128), 256, GEMM_SMEM>>>(Ch, Cl, wo, out);
}